// round 2
// baseline (speedup 1.0000x reference)
#include <cuda_runtime.h>
#include <math.h>

#define DIMC 1536
#define NHEADS 12
#define HD 128
#define MAX_ATTN_W 5632
#define MAXS 3200

// Scratch (allocation-free rule: __device__ globals)
__device__ float g_q[MAXS * DIMC];
__device__ float g_k[MAXS * DIMC];
__device__ float g_v[MAXS * DIMC];
__device__ float g_o[MAXS * DIMC];

// ---------------------------------------------------------------------------
// GEMM: C[M,1536] = A[M,1536] @ W[1536,1536]^T + bias   (both K-major)
// 64x64 tile, BK=16, 256 threads, 4x4 micro-tile.
// ---------------------------------------------------------------------------
__global__ __launch_bounds__(256) void gemm_bias_kernel(
    const float* __restrict__ A, const float* __restrict__ W,
    const float* __restrict__ bias, float* __restrict__ C, int M)
{
    __shared__ float As[16][68];
    __shared__ float Bs[16][68];

    int tid = threadIdx.x;
    int ty = tid >> 4, tx = tid & 15;
    int ar = tid >> 2;            // 0..63
    int ak = (tid & 3) * 4;       // 0,4,8,12
    int am = blockIdx.x * 64 + ar;
    int wn = blockIdx.y * 64 + ar;
    bool avalid = (am < M);
    const float4* Ap = (const float4*)(A + (size_t)am * DIMC + ak);
    const float4* Wp = (const float4*)(W + (size_t)wn * DIMC + ak);

    float acc[4][4];
#pragma unroll
    for (int i = 0; i < 4; i++)
#pragma unroll
        for (int j = 0; j < 4; j++) acc[i][j] = 0.0f;

    for (int kt = 0; kt < DIMC / 16; kt++) {
        float4 a4 = avalid ? Ap[kt * 4] : make_float4(0.f, 0.f, 0.f, 0.f);
        float4 b4 = Wp[kt * 4];
        __syncthreads();
        As[ak + 0][ar] = a4.x; As[ak + 1][ar] = a4.y;
        As[ak + 2][ar] = a4.z; As[ak + 3][ar] = a4.w;
        Bs[ak + 0][ar] = b4.x; Bs[ak + 1][ar] = b4.y;
        Bs[ak + 2][ar] = b4.z; Bs[ak + 3][ar] = b4.w;
        __syncthreads();
#pragma unroll
        for (int k = 0; k < 16; k++) {
            float4 av = *(const float4*)(&As[k][ty * 4]);
            float4 bv = *(const float4*)(&Bs[k][tx * 4]);
            float a_[4] = {av.x, av.y, av.z, av.w};
            float b_[4] = {bv.x, bv.y, bv.z, bv.w};
#pragma unroll
            for (int i = 0; i < 4; i++)
#pragma unroll
                for (int j = 0; j < 4; j++)
                    acc[i][j] = fmaf(a_[i], b_[j], acc[i][j]);
        }
    }

    int m0 = blockIdx.x * 64 + ty * 4;
    int n0 = blockIdx.y * 64 + tx * 4;
#pragma unroll
    for (int i = 0; i < 4; i++) {
        if (m0 + i < M) {
#pragma unroll
            for (int j = 0; j < 4; j++)
                C[(size_t)(m0 + i) * DIMC + n0 + j] = acc[i][j] + bias[n0 + j];
        }
    }
}

// ---------------------------------------------------------------------------
// RMSNorm (over full 1536) + 3-axis causal RoPE, in-place on q and k buffers.
// blockIdx.x = sequence row, blockIdx.y = 0 (q) / 1 (k). 256 threads.
// ---------------------------------------------------------------------------
__global__ __launch_bounds__(256) void norm_rope_kernel(
    float* __restrict__ qb, float* __restrict__ kb,
    const float* __restrict__ gq, const float* __restrict__ gk,
    const float* __restrict__ theta,
    const int* __restrict__ p_gh, const int* __restrict__ p_gw,
    const int* __restrict__ p_cs)
{
    __shared__ float row[DIMC];
    __shared__ float red[256];

    int srow = blockIdx.x;
    int which = blockIdx.y;
    float* buf = which ? kb : qb;
    const float* g = which ? gk : gq;
    float* rptr = buf + (size_t)srow * DIMC;

    int tid = threadIdx.x;
    float vals[6];
    float ss = 0.0f;
#pragma unroll
    for (int q = 0; q < 6; q++) {
        int d = tid + q * 256;
        float v = rptr[d];
        vals[q] = v;
        ss += v * v;
    }
    red[tid] = ss;
    __syncthreads();
    for (int o = 128; o > 0; o >>= 1) {
        if (tid < o) red[tid] += red[tid + o];
        __syncthreads();
    }
    float scale = rsqrtf(red[0] * (1.0f / DIMC) + 1e-6f);
#pragma unroll
    for (int q = 0; q < 6; q++) {
        int d = tid + q * 256;
        row[d] = vals[q] * scale * g[d];
    }
    __syncthreads();

    int gh = *p_gh, gw = *p_gw, cs = *p_cs;
    int fs = gh * gw;
    int sf = cs / fs;                 // start_frame
    int f = srow / fs;
    int rem = srow - f * fs;
    int h = rem / gw;
    int w = rem - h * gw;

    // 12 heads * 64 pairs = 768 pairs
    for (int p = tid; p < NHEADS * (HD / 2); p += 256) {
        int head = p >> 6;
        int i = p & 63;
        int trow = (i < 22) ? (sf + f) : ((i < 43) ? h : w);
        float ang = theta[trow * (HD / 2) + i];
        float sn, cn;
        __sincosf(ang, &sn, &cn);
        int d0 = head * HD + 2 * i;
        float xr = row[d0], xi = row[d0 + 1];
        rptr[d0]     = xr * cn - xi * sn;
        rptr[d0 + 1] = xr * sn + xi * cn;
    }
}

// ---------------------------------------------------------------------------
// Flash attention over the KV window. Window keys come from cache (< local_start)
// or freshly computed k/v buffers (>= local_start). BM=BN=64, 256 threads.
// K tile XOR-swizzled in smem; Q/V plain (stride 132 pads fix banks).
// ---------------------------------------------------------------------------
__global__ __launch_bounds__(256) void flash_kernel(
    const float* __restrict__ qbuf, const float* __restrict__ kbuf,
    const float* __restrict__ vbuf, const float* __restrict__ cache_k,
    const float* __restrict__ cache_v, float* __restrict__ obuf, int S,
    const int* __restrict__ p_cs, const int* __restrict__ p_ge,
    const int* __restrict__ p_le)
{
    extern __shared__ float sm[];
    float* Qs  = sm;                  // 64 * 132
    float* KVs = sm + 64 * 132;       // 64 * 132
    float* Ps  = sm + 2 * 64 * 132;   // 64 * 68

    int cs = *p_cs, ge = *p_ge, le = *p_le;
    int local_end = le + cs + S - ge;
    int local_start = local_end - S;
    int win_start = local_end - MAX_ATTN_W;
    if (win_start < 0) win_start = 0;
    int L = local_end - win_start;

    int hh = blockIdx.y;
    int qbase = blockIdx.x * 64;
    int tid = threadIdx.x;
    int ty = tid >> 4, tx = tid & 15;
    int m0 = ty * 4;

    // Load Q tile (plain layout)
    for (int idx = tid; idx < 64 * 32; idx += 256) {
        int r = idx >> 5, c4 = idx & 31;
        int m = qbase + r;
        float4 v4 = make_float4(0.f, 0.f, 0.f, 0.f);
        if (m < S)
            v4 = *(const float4*)(qbuf + (size_t)m * DIMC + hh * HD + c4 * 4);
        *(float4*)(Qs + r * 132 + c4 * 4) = v4;
    }

    float mst[4], lst[4], oacc[4][8];
#pragma unroll
    for (int i = 0; i < 4; i++) {
        mst[i] = -1e30f; lst[i] = 0.0f;
#pragma unroll
        for (int j = 0; j < 8; j++) oacc[i][j] = 0.0f;
    }

    const float scale = 0.08838834764831845f;  // 1/sqrt(128)
    int nkt = (L + 63) >> 6;

    for (int kt = 0; kt < nkt; kt++) {
        __syncthreads();  // V reads of prev iter done (and Q load on iter 0)
        // ---- load K tile, swizzled ----
        for (int idx = tid; idx < 64 * 32; idx += 256) {
            int r = idx >> 5, c4 = idx & 31;
            int jg = win_start + kt * 64 + r;
            float4 v4 = make_float4(0.f, 0.f, 0.f, 0.f);
            if (jg < local_end) {
                if (jg < local_start)
                    v4 = *(const float4*)(cache_k + ((size_t)jg * NHEADS + hh) * HD + c4 * 4);
                else
                    v4 = *(const float4*)(kbuf + (size_t)(jg - local_start) * DIMC + hh * HD + c4 * 4);
            }
            int p = c4 ^ ((r >> 2) & 7);
            *(float4*)(KVs + r * 132 + p * 4) = v4;
        }
        __syncthreads();

        // ---- scores S = Q * K^T ----
        float s[4][4];
#pragma unroll
        for (int i = 0; i < 4; i++)
#pragma unroll
            for (int j = 0; j < 4; j++) s[i][j] = 0.0f;

        int swz = tx & 7;
#pragma unroll 4
        for (int d4 = 0; d4 < 32; d4++) {
            float4 a0 = *(const float4*)(Qs + (m0 + 0) * 132 + d4 * 4);
            float4 a1 = *(const float4*)(Qs + (m0 + 1) * 132 + d4 * 4);
            float4 a2 = *(const float4*)(Qs + (m0 + 2) * 132 + d4 * 4);
            float4 a3 = *(const float4*)(Qs + (m0 + 3) * 132 + d4 * 4);
            int kp = (d4 ^ swz) * 4;
            float4 b0 = *(const float4*)(KVs + (tx * 4 + 0) * 132 + kp);
            float4 b1 = *(const float4*)(KVs + (tx * 4 + 1) * 132 + kp);
            float4 b2 = *(const float4*)(KVs + (tx * 4 + 2) * 132 + kp);
            float4 b3 = *(const float4*)(KVs + (tx * 4 + 3) * 132 + kp);
            float av[4][4] = {{a0.x,a0.y,a0.z,a0.w},{a1.x,a1.y,a1.z,a1.w},
                              {a2.x,a2.y,a2.z,a2.w},{a3.x,a3.y,a3.z,a3.w}};
            float bv[4][4] = {{b0.x,b0.y,b0.z,b0.w},{b1.x,b1.y,b1.z,b1.w},
                              {b2.x,b2.y,b2.z,b2.w},{b3.x,b3.y,b3.z,b3.w}};
#pragma unroll
            for (int i = 0; i < 4; i++)
#pragma unroll
                for (int j = 0; j < 4; j++) {
                    s[i][j] = fmaf(av[i][0], bv[j][0], s[i][j]);
                    s[i][j] = fmaf(av[i][1], bv[j][1], s[i][j]);
                    s[i][j] = fmaf(av[i][2], bv[j][2], s[i][j]);
                    s[i][j] = fmaf(av[i][3], bv[j][3], s[i][j]);
                }
        }

        // ---- online softmax ----
        int cbase = kt * 64 + tx * 4;
#pragma unroll
        for (int i = 0; i < 4; i++) {
#pragma unroll
            for (int j = 0; j < 4; j++) {
                s[i][j] *= scale;
                if (cbase + j >= L) s[i][j] = -1e30f;
            }
            float m4 = fmaxf(fmaxf(s[i][0], s[i][1]), fmaxf(s[i][2], s[i][3]));
#pragma unroll
            for (int o = 8; o > 0; o >>= 1)
                m4 = fmaxf(m4, __shfl_xor_sync(0xffffffffu, m4, o, 16));
            float newm = fmaxf(mst[i], m4);
            float fac = __expf(mst[i] - newm);
            mst[i] = newm;
            float4 pv;
            pv.x = __expf(s[i][0] - newm);
            pv.y = __expf(s[i][1] - newm);
            pv.z = __expf(s[i][2] - newm);
            pv.w = __expf(s[i][3] - newm);
            *(float4*)(Ps + (m0 + i) * 68 + tx * 4) = pv;
            float rs = pv.x + pv.y + pv.z + pv.w;
#pragma unroll
            for (int o = 8; o > 0; o >>= 1)
                rs += __shfl_xor_sync(0xffffffffu, rs, o, 16);
            lst[i] = lst[i] * fac + rs;
#pragma unroll
            for (int j = 0; j < 8; j++) oacc[i][j] *= fac;
        }
        __syncthreads();  // Ps written, K reads done

        // ---- load V tile (plain layout, overwrites K buffer) ----
        for (int idx = tid; idx < 64 * 32; idx += 256) {
            int r = idx >> 5, c4 = idx & 31;
            int jg = win_start + kt * 64 + r;
            float4 v4 = make_float4(0.f, 0.f, 0.f, 0.f);
            if (jg < local_end) {
                if (jg < local_start)
                    v4 = *(const float4*)(cache_v + ((size_t)jg * NHEADS + hh) * HD + c4 * 4);
                else
                    v4 = *(const float4*)(vbuf + (size_t)(jg - local_start) * DIMC + hh * HD + c4 * 4);
            }
            *(float4*)(KVs + r * 132 + c4 * 4) = v4;
        }
        __syncthreads();

        // ---- O += P * V ----  (thread cols: tx + 16*j)
        for (int n = 0; n < 64; n++) {
            float p0 = Ps[(m0 + 0) * 68 + n];
            float p1 = Ps[(m0 + 1) * 68 + n];
            float p2 = Ps[(m0 + 2) * 68 + n];
            float p3 = Ps[(m0 + 3) * 68 + n];
            const float* vr = KVs + n * 132 + tx;
#pragma unroll
            for (int j = 0; j < 8; j++) {
                float v = vr[j * 16];
                oacc[0][j] = fmaf(p0, v, oacc[0][j]);
                oacc[1][j] = fmaf(p1, v, oacc[1][j]);
                oacc[2][j] = fmaf(p2, v, oacc[2][j]);
                oacc[3][j] = fmaf(p3, v, oacc[3][j]);
            }
        }
    }

    // ---- epilogue ----
#pragma unroll
    for (int i = 0; i < 4; i++) {
        int m = qbase + m0 + i;
        if (m < S) {
            float inv = 1.0f / lst[i];
            float* op = obuf + (size_t)m * DIMC + hh * HD + tx;
#pragma unroll
            for (int j = 0; j < 8; j++)
                op[j * 16] = oacc[i][j] * inv;
        }
    }
}

// ---------------------------------------------------------------------------
extern "C" void kernel_launch(void* const* d_in, const int* in_sizes, int n_in,
                              void* d_out, int out_size)
{
    const float* x   = (const float*)d_in[0];
    const float* th  = (const float*)d_in[1];
    const float* ck  = (const float*)d_in[2];
    const float* cv  = (const float*)d_in[3];
    const float* wq  = (const float*)d_in[4];
    const float* bq  = (const float*)d_in[5];
    const float* wk  = (const float*)d_in[6];
    const float* bk  = (const float*)d_in[7];
    const float* wv  = (const float*)d_in[8];
    const float* bv  = (const float*)d_in[9];
    const float* wo  = (const float*)d_in[10];
    const float* bo  = (const float*)d_in[11];
    const float* gq  = (const float*)d_in[12];
    const float* gk  = (const float*)d_in[13];
    // d_in[14] = grid_f (unused; frame index derived from row)
    const int* p_gh  = (const int*)d_in[15];
    const int* p_gw  = (const int*)d_in[16];
    const int* p_cs  = (const int*)d_in[17];
    const int* p_ge  = (const int*)d_in[18];
    const int* p_le  = (const int*)d_in[19];
    float* out = (float*)d_out;

    int S = in_sizes[0] / DIMC;

    float *qp, *kp, *vp, *op;
    cudaGetSymbolAddress((void**)&qp, g_q);
    cudaGetSymbolAddress((void**)&kp, g_k);
    cudaGetSymbolAddress((void**)&vp, g_v);
    cudaGetSymbolAddress((void**)&op, g_o);

    dim3 gg((S + 63) / 64, DIMC / 64);

    gemm_bias_kernel<<<gg, 256>>>(x, wq, bq, qp, S);
    gemm_bias_kernel<<<gg, 256>>>(x, wk, bk, kp, S);
    gemm_bias_kernel<<<gg, 256>>>(x, wv, bv, vp, S);

    norm_rope_kernel<<<dim3(S, 2), 256>>>(qp, kp, gq, gk, th, p_gh, p_gw, p_cs);

    size_t smem = (size_t)(2 * 64 * 132 + 64 * 68) * sizeof(float);  // ~85 KB
    cudaFuncSetAttribute(flash_kernel, cudaFuncAttributeMaxDynamicSharedMemorySize,
                         (int)smem);
    flash_kernel<<<dim3((S + 63) / 64, NHEADS), 256, smem>>>(
        qp, kp, vp, ck, cv, op, S, p_cs, p_ge, p_le);

    gemm_bias_kernel<<<gg, 256>>>(op, wo, bo, out, S);
}

// round 3
// speedup vs baseline: 1.0052x; 1.0052x over previous
#include <cuda_runtime.h>
#include <math.h>

#define DIMC 1536
#define NHEADS 12
#define HD 128
#define MAX_ATTN_W 5632
#define MAXS 3200

// Scratch (allocation-free rule: __device__ globals)
__device__ float g_q[MAXS * DIMC];
__device__ float g_k[MAXS * DIMC];
__device__ float g_v[MAXS * DIMC];
__device__ float g_o[MAXS * DIMC];

// ---------------------------------------------------------------------------
// GEMM: C[M,1536] = A[M,1536] @ W[1536,1536]^T + bias   (both K-major)
// 64x64 tile, BK=16, 256 threads, 4x4 micro-tile.
// ---------------------------------------------------------------------------
__global__ __launch_bounds__(256) void gemm_bias_kernel(
    const float* __restrict__ A, const float* __restrict__ W,
    const float* __restrict__ bias, float* __restrict__ C, int M)
{
    __shared__ float As[16][68];
    __shared__ float Bs[16][68];

    int tid = threadIdx.x;
    int ty = tid >> 4, tx = tid & 15;
    int ar = tid >> 2;            // 0..63
    int ak = (tid & 3) * 4;       // 0,4,8,12
    int am = blockIdx.x * 64 + ar;
    int wn = blockIdx.y * 64 + ar;
    bool avalid = (am < M);
    const float4* Ap = (const float4*)(A + (size_t)am * DIMC + ak);
    const float4* Wp = (const float4*)(W + (size_t)wn * DIMC + ak);

    float acc[4][4];
#pragma unroll
    for (int i = 0; i < 4; i++)
#pragma unroll
        for (int j = 0; j < 4; j++) acc[i][j] = 0.0f;

    for (int kt = 0; kt < DIMC / 16; kt++) {
        float4 a4 = avalid ? Ap[kt * 4] : make_float4(0.f, 0.f, 0.f, 0.f);
        float4 b4 = Wp[kt * 4];
        __syncthreads();
        As[ak + 0][ar] = a4.x; As[ak + 1][ar] = a4.y;
        As[ak + 2][ar] = a4.z; As[ak + 3][ar] = a4.w;
        Bs[ak + 0][ar] = b4.x; Bs[ak + 1][ar] = b4.y;
        Bs[ak + 2][ar] = b4.z; Bs[ak + 3][ar] = b4.w;
        __syncthreads();
#pragma unroll
        for (int k = 0; k < 16; k++) {
            float4 av = *(const float4*)(&As[k][ty * 4]);
            float4 bv = *(const float4*)(&Bs[k][tx * 4]);
            float a_[4] = {av.x, av.y, av.z, av.w};
            float b_[4] = {bv.x, bv.y, bv.z, bv.w};
#pragma unroll
            for (int i = 0; i < 4; i++)
#pragma unroll
                for (int j = 0; j < 4; j++)
                    acc[i][j] = fmaf(a_[i], b_[j], acc[i][j]);
        }
    }

    int m0 = blockIdx.x * 64 + ty * 4;
    int n0 = blockIdx.y * 64 + tx * 4;
#pragma unroll
    for (int i = 0; i < 4; i++) {
        if (m0 + i < M) {
#pragma unroll
            for (int j = 0; j < 4; j++)
                C[(size_t)(m0 + i) * DIMC + n0 + j] = acc[i][j] + bias[n0 + j];
        }
    }
}

// ---------------------------------------------------------------------------
// RMSNorm (over full 1536) + 3-axis causal RoPE, in-place on q and k buffers.
// blockIdx.x = sequence row, blockIdx.y = 0 (q) / 1 (k). 256 threads.
// ---------------------------------------------------------------------------
__global__ __launch_bounds__(256) void norm_rope_kernel(
    float* __restrict__ qb, float* __restrict__ kb,
    const float* __restrict__ gq, const float* __restrict__ gk,
    const float* __restrict__ theta,
    const int* __restrict__ p_gh, const int* __restrict__ p_gw,
    const int* __restrict__ p_cs)
{
    __shared__ float row[DIMC];
    __shared__ float red[256];

    int srow = blockIdx.x;
    int which = blockIdx.y;
    float* buf = which ? kb : qb;
    const float* g = which ? gk : gq;
    float* rptr = buf + (size_t)srow * DIMC;

    int tid = threadIdx.x;
    float vals[6];
    float ss = 0.0f;
#pragma unroll
    for (int q = 0; q < 6; q++) {
        int d = tid + q * 256;
        float v = rptr[d];
        vals[q] = v;
        ss += v * v;
    }
    red[tid] = ss;
    __syncthreads();
    for (int o = 128; o > 0; o >>= 1) {
        if (tid < o) red[tid] += red[tid + o];
        __syncthreads();
    }
    float scale = rsqrtf(red[0] * (1.0f / DIMC) + 1e-6f);
#pragma unroll
    for (int q = 0; q < 6; q++) {
        int d = tid + q * 256;
        row[d] = vals[q] * scale * g[d];
    }
    __syncthreads();

    int gh = *p_gh, gw = *p_gw, cs = *p_cs;
    int fs = gh * gw;
    int sf = cs / fs;                 // start_frame
    int f = srow / fs;
    int rem = srow - f * fs;
    int h = rem / gw;
    int w = rem - h * gw;

    // 12 heads * 64 pairs = 768 pairs
    for (int p = tid; p < NHEADS * (HD / 2); p += 256) {
        int head = p >> 6;
        int i = p & 63;
        int trow = (i < 22) ? (sf + f) : ((i < 43) ? h : w);
        float ang = theta[trow * (HD / 2) + i];
        float sn, cn;
        __sincosf(ang, &sn, &cn);
        int d0 = head * HD + 2 * i;
        float xr = row[d0], xi = row[d0 + 1];
        rptr[d0]     = xr * cn - xi * sn;
        rptr[d0 + 1] = xr * sn + xi * cn;
    }
}

// ---------------------------------------------------------------------------
// Flash attention over the KV window. Window keys come from cache (< local_start)
// or freshly computed k/v buffers (>= local_start). BM=BN=64, 256 threads.
// K tile XOR-swizzled in smem; Q/V plain (stride 132 pads fix banks).
// ---------------------------------------------------------------------------
__global__ __launch_bounds__(256) void flash_kernel(
    const float* __restrict__ qbuf, const float* __restrict__ kbuf,
    const float* __restrict__ vbuf, const float* __restrict__ cache_k,
    const float* __restrict__ cache_v, float* __restrict__ obuf, int S,
    const int* __restrict__ p_cs, const int* __restrict__ p_ge,
    const int* __restrict__ p_le)
{
    extern __shared__ float sm[];
    float* Qs  = sm;                  // 64 * 132
    float* KVs = sm + 64 * 132;       // 64 * 132
    float* Ps  = sm + 2 * 64 * 132;   // 64 * 68

    int cs = *p_cs, ge = *p_ge, le = *p_le;
    int local_end = le + cs + S - ge;
    int local_start = local_end - S;
    int win_start = local_end - MAX_ATTN_W;
    if (win_start < 0) win_start = 0;
    int L = local_end - win_start;

    int hh = blockIdx.y;
    int qbase = blockIdx.x * 64;
    int tid = threadIdx.x;
    int ty = tid >> 4, tx = tid & 15;
    int m0 = ty * 4;

    // Load Q tile (plain layout)
    for (int idx = tid; idx < 64 * 32; idx += 256) {
        int r = idx >> 5, c4 = idx & 31;
        int m = qbase + r;
        float4 v4 = make_float4(0.f, 0.f, 0.f, 0.f);
        if (m < S)
            v4 = *(const float4*)(qbuf + (size_t)m * DIMC + hh * HD + c4 * 4);
        *(float4*)(Qs + r * 132 + c4 * 4) = v4;
    }

    float mst[4], lst[4], oacc[4][8];
#pragma unroll
    for (int i = 0; i < 4; i++) {
        mst[i] = -1e30f; lst[i] = 0.0f;
#pragma unroll
        for (int j = 0; j < 8; j++) oacc[i][j] = 0.0f;
    }

    const float scale = 0.08838834764831845f;  // 1/sqrt(128)
    int nkt = (L + 63) >> 6;

    for (int kt = 0; kt < nkt; kt++) {
        __syncthreads();  // V reads of prev iter done (and Q load on iter 0)
        // ---- load K tile, swizzled ----
        for (int idx = tid; idx < 64 * 32; idx += 256) {
            int r = idx >> 5, c4 = idx & 31;
            int jg = win_start + kt * 64 + r;
            float4 v4 = make_float4(0.f, 0.f, 0.f, 0.f);
            if (jg < local_end) {
                if (jg < local_start)
                    v4 = *(const float4*)(cache_k + ((size_t)jg * NHEADS + hh) * HD + c4 * 4);
                else
                    v4 = *(const float4*)(kbuf + (size_t)(jg - local_start) * DIMC + hh * HD + c4 * 4);
            }
            int p = c4 ^ ((r >> 2) & 7);
            *(float4*)(KVs + r * 132 + p * 4) = v4;
        }
        __syncthreads();

        // ---- scores S = Q * K^T ----
        float s[4][4];
#pragma unroll
        for (int i = 0; i < 4; i++)
#pragma unroll
            for (int j = 0; j < 4; j++) s[i][j] = 0.0f;

        int swz = tx & 7;
#pragma unroll 4
        for (int d4 = 0; d4 < 32; d4++) {
            float4 a0 = *(const float4*)(Qs + (m0 + 0) * 132 + d4 * 4);
            float4 a1 = *(const float4*)(Qs + (m0 + 1) * 132 + d4 * 4);
            float4 a2 = *(const float4*)(Qs + (m0 + 2) * 132 + d4 * 4);
            float4 a3 = *(const float4*)(Qs + (m0 + 3) * 132 + d4 * 4);
            int kp = (d4 ^ swz) * 4;
            float4 b0 = *(const float4*)(KVs + (tx * 4 + 0) * 132 + kp);
            float4 b1 = *(const float4*)(KVs + (tx * 4 + 1) * 132 + kp);
            float4 b2 = *(const float4*)(KVs + (tx * 4 + 2) * 132 + kp);
            float4 b3 = *(const float4*)(KVs + (tx * 4 + 3) * 132 + kp);
            float av[4][4] = {{a0.x,a0.y,a0.z,a0.w},{a1.x,a1.y,a1.z,a1.w},
                              {a2.x,a2.y,a2.z,a2.w},{a3.x,a3.y,a3.z,a3.w}};
            float bv[4][4] = {{b0.x,b0.y,b0.z,b0.w},{b1.x,b1.y,b1.z,b1.w},
                              {b2.x,b2.y,b2.z,b2.w},{b3.x,b3.y,b3.z,b3.w}};
#pragma unroll
            for (int i = 0; i < 4; i++)
#pragma unroll
                for (int j = 0; j < 4; j++) {
                    s[i][j] = fmaf(av[i][0], bv[j][0], s[i][j]);
                    s[i][j] = fmaf(av[i][1], bv[j][1], s[i][j]);
                    s[i][j] = fmaf(av[i][2], bv[j][2], s[i][j]);
                    s[i][j] = fmaf(av[i][3], bv[j][3], s[i][j]);
                }
        }

        // ---- online softmax ----
        int cbase = kt * 64 + tx * 4;
#pragma unroll
        for (int i = 0; i < 4; i++) {
#pragma unroll
            for (int j = 0; j < 4; j++) {
                s[i][j] *= scale;
                if (cbase + j >= L) s[i][j] = -1e30f;
            }
            float m4 = fmaxf(fmaxf(s[i][0], s[i][1]), fmaxf(s[i][2], s[i][3]));
#pragma unroll
            for (int o = 8; o > 0; o >>= 1)
                m4 = fmaxf(m4, __shfl_xor_sync(0xffffffffu, m4, o, 16));
            float newm = fmaxf(mst[i], m4);
            float fac = __expf(mst[i] - newm);
            mst[i] = newm;
            float4 pv;
            pv.x = __expf(s[i][0] - newm);
            pv.y = __expf(s[i][1] - newm);
            pv.z = __expf(s[i][2] - newm);
            pv.w = __expf(s[i][3] - newm);
            *(float4*)(Ps + (m0 + i) * 68 + tx * 4) = pv;
            float rs = pv.x + pv.y + pv.z + pv.w;
#pragma unroll
            for (int o = 8; o > 0; o >>= 1)
                rs += __shfl_xor_sync(0xffffffffu, rs, o, 16);
            lst[i] = lst[i] * fac + rs;
#pragma unroll
            for (int j = 0; j < 8; j++) oacc[i][j] *= fac;
        }
        __syncthreads();  // Ps written, K reads done

        // ---- load V tile (plain layout, overwrites K buffer) ----
        for (int idx = tid; idx < 64 * 32; idx += 256) {
            int r = idx >> 5, c4 = idx & 31;
            int jg = win_start + kt * 64 + r;
            float4 v4 = make_float4(0.f, 0.f, 0.f, 0.f);
            if (jg < local_end) {
                if (jg < local_start)
                    v4 = *(const float4*)(cache_v + ((size_t)jg * NHEADS + hh) * HD + c4 * 4);
                else
                    v4 = *(const float4*)(vbuf + (size_t)(jg - local_start) * DIMC + hh * HD + c4 * 4);
            }
            *(float4*)(KVs + r * 132 + c4 * 4) = v4;
        }
        __syncthreads();

        // ---- O += P * V ----  (thread cols: tx + 16*j)
        for (int n = 0; n < 64; n++) {
            float p0 = Ps[(m0 + 0) * 68 + n];
            float p1 = Ps[(m0 + 1) * 68 + n];
            float p2 = Ps[(m0 + 2) * 68 + n];
            float p3 = Ps[(m0 + 3) * 68 + n];
            const float* vr = KVs + n * 132 + tx;
#pragma unroll
            for (int j = 0; j < 8; j++) {
                float v = vr[j * 16];
                oacc[0][j] = fmaf(p0, v, oacc[0][j]);
                oacc[1][j] = fmaf(p1, v, oacc[1][j]);
                oacc[2][j] = fmaf(p2, v, oacc[2][j]);
                oacc[3][j] = fmaf(p3, v, oacc[3][j]);
            }
        }
    }

    // ---- epilogue ----
#pragma unroll
    for (int i = 0; i < 4; i++) {
        int m = qbase + m0 + i;
        if (m < S) {
            float inv = 1.0f / lst[i];
            float* op = obuf + (size_t)m * DIMC + hh * HD + tx;
#pragma unroll
            for (int j = 0; j < 8; j++)
                op[j * 16] = oacc[i][j] * inv;
        }
    }
}

// ---------------------------------------------------------------------------
extern "C" void kernel_launch(void* const* d_in, const int* in_sizes, int n_in,
                              void* d_out, int out_size)
{
    const float* x   = (const float*)d_in[0];
    const float* th  = (const float*)d_in[1];
    const float* ck  = (const float*)d_in[2];
    const float* cv  = (const float*)d_in[3];
    const float* wq  = (const float*)d_in[4];
    const float* bq  = (const float*)d_in[5];
    const float* wk  = (const float*)d_in[6];
    const float* bk  = (const float*)d_in[7];
    const float* wv  = (const float*)d_in[8];
    const float* bv  = (const float*)d_in[9];
    const float* wo  = (const float*)d_in[10];
    const float* bo  = (const float*)d_in[11];
    const float* gq  = (const float*)d_in[12];
    const float* gk  = (const float*)d_in[13];
    // d_in[14] = grid_f (unused; frame index derived from row)
    const int* p_gh  = (const int*)d_in[15];
    const int* p_gw  = (const int*)d_in[16];
    const int* p_cs  = (const int*)d_in[17];
    const int* p_ge  = (const int*)d_in[18];
    const int* p_le  = (const int*)d_in[19];
    float* out = (float*)d_out;

    int S = in_sizes[0] / DIMC;

    float *qp, *kp, *vp, *op;
    cudaGetSymbolAddress((void**)&qp, g_q);
    cudaGetSymbolAddress((void**)&kp, g_k);
    cudaGetSymbolAddress((void**)&vp, g_v);
    cudaGetSymbolAddress((void**)&op, g_o);

    dim3 gg((S + 63) / 64, DIMC / 64);

    gemm_bias_kernel<<<gg, 256>>>(x, wq, bq, qp, S);
    gemm_bias_kernel<<<gg, 256>>>(x, wk, bk, kp, S);
    gemm_bias_kernel<<<gg, 256>>>(x, wv, bv, vp, S);

    norm_rope_kernel<<<dim3(S, 2), 256>>>(qp, kp, gq, gk, th, p_gh, p_gw, p_cs);

    size_t smem = (size_t)(2 * 64 * 132 + 64 * 68) * sizeof(float);  // ~85 KB
    cudaFuncSetAttribute(flash_kernel, cudaFuncAttributeMaxDynamicSharedMemorySize,
                         (int)smem);
    flash_kernel<<<dim3((S + 63) / 64, NHEADS), 256, smem>>>(
        qp, kp, vp, ck, cv, op, S, p_cs, p_ge, p_le);

    gemm_bias_kernel<<<gg, 256>>>(op, wo, bo, out, S);
}

// round 4
// speedup vs baseline: 2.1348x; 2.1238x over previous
#include <cuda_runtime.h>
#include <math.h>

#define DIMC 1536
#define NHEADS 12
#define HD 128
#define MAX_ATTN_W 5632
#define MAXS 3200

__device__ float g_q[MAXS * DIMC];
__device__ float g_k[MAXS * DIMC];
__device__ float g_v[MAXS * DIMC];
__device__ float g_o[MAXS * DIMC];

__device__ __forceinline__ unsigned f2tf(float x) {
    unsigned u; asm("cvt.rna.tf32.f32 %0, %1;" : "=r"(u) : "f"(x)); return u;
}
__device__ __forceinline__ float f2tff(float x) { return __uint_as_float(f2tf(x)); }

__device__ __forceinline__ void mma_tf32(float* d, const unsigned* a,
                                         unsigned b0, unsigned b1) {
    asm volatile(
        "mma.sync.aligned.m16n8k8.row.col.f32.tf32.tf32.f32 "
        "{%0,%1,%2,%3}, {%4,%5,%6,%7}, {%8,%9}, {%0,%1,%2,%3};\n"
        : "+f"(d[0]), "+f"(d[1]), "+f"(d[2]), "+f"(d[3])
        : "r"(a[0]), "r"(a[1]), "r"(a[2]), "r"(a[3]), "r"(b0), "r"(b1));
}

// ---------------------------------------------------------------------------
// GEMM: C[M,1536] = A[M,1536] @ W[1536,1536]^T + bias, tf32 tensor cores.
// BM=BN=128, BK=16, 256 threads (8 warps, 32x64 warp tiles).
// smem [row][k] stride 20 floats: frag loads bank-conflict-free.
// ---------------------------------------------------------------------------
__global__ __launch_bounds__(256) void gemm_tc_kernel(
    const float* __restrict__ A, const float* __restrict__ W,
    const float* __restrict__ bias, float* __restrict__ C, int M)
{
    __shared__ float As[128 * 20];
    __shared__ float Bs[128 * 20];

    int tid = threadIdx.x, warp = tid >> 5, lane = tid & 31;
    int g = lane >> 2, t = lane & 3;
    int wm = (warp & 3) * 32, wn = (warp >> 2) * 64;
    int bm = blockIdx.x * 128, bn = blockIdx.y * 128;

    float acc[2][8][4];
#pragma unroll
    for (int mt = 0; mt < 2; mt++)
#pragma unroll
        for (int nt = 0; nt < 8; nt++)
#pragma unroll
            for (int i = 0; i < 4; i++) acc[mt][nt][i] = 0.0f;

    int frow = tid >> 2, fk0 = (tid & 3) * 4;
    int ar0 = bm + frow, ar1 = bm + frow + 64;
    const float* Ap0 = A + (size_t)ar0 * DIMC + fk0;
    const float* Ap1 = A + (size_t)ar1 * DIMC + fk0;
    const float* Wp0 = W + (size_t)(bn + frow) * DIMC + fk0;
    const float* Wp1 = W + (size_t)(bn + frow + 64) * DIMC + fk0;
    bool av0 = ar0 < M, av1 = ar1 < M;

    for (int kt = 0; kt < DIMC / 16; kt++) {
        float4 z4 = make_float4(0.f, 0.f, 0.f, 0.f);
        float4 a0 = av0 ? *(const float4*)(Ap0 + kt * 16) : z4;
        float4 a1 = av1 ? *(const float4*)(Ap1 + kt * 16) : z4;
        float4 b0 = *(const float4*)(Wp0 + kt * 16);
        float4 b1 = *(const float4*)(Wp1 + kt * 16);
        __syncthreads();
        a0.x = f2tff(a0.x); a0.y = f2tff(a0.y); a0.z = f2tff(a0.z); a0.w = f2tff(a0.w);
        a1.x = f2tff(a1.x); a1.y = f2tff(a1.y); a1.z = f2tff(a1.z); a1.w = f2tff(a1.w);
        b0.x = f2tff(b0.x); b0.y = f2tff(b0.y); b0.z = f2tff(b0.z); b0.w = f2tff(b0.w);
        b1.x = f2tff(b1.x); b1.y = f2tff(b1.y); b1.z = f2tff(b1.z); b1.w = f2tff(b1.w);
        *(float4*)(As + frow * 20 + fk0) = a0;
        *(float4*)(As + (frow + 64) * 20 + fk0) = a1;
        *(float4*)(Bs + frow * 20 + fk0) = b0;
        *(float4*)(Bs + (frow + 64) * 20 + fk0) = b1;
        __syncthreads();
#pragma unroll
        for (int kst = 0; kst < 2; kst++) {
            int k0 = kst * 8 + t;
            unsigned af[2][4];
#pragma unroll
            for (int mt = 0; mt < 2; mt++) {
                int m0 = wm + mt * 16 + g;
                af[mt][0] = __float_as_uint(As[m0 * 20 + k0]);
                af[mt][1] = __float_as_uint(As[(m0 + 8) * 20 + k0]);
                af[mt][2] = __float_as_uint(As[m0 * 20 + k0 + 4]);
                af[mt][3] = __float_as_uint(As[(m0 + 8) * 20 + k0 + 4]);
            }
#pragma unroll
            for (int nt = 0; nt < 8; nt++) {
                int n = wn + nt * 8 + g;
                unsigned bf0 = __float_as_uint(Bs[n * 20 + k0]);
                unsigned bf1 = __float_as_uint(Bs[n * 20 + k0 + 4]);
                mma_tf32(acc[0][nt], af[0], bf0, bf1);
                mma_tf32(acc[1][nt], af[1], bf0, bf1);
            }
        }
    }
#pragma unroll
    for (int mt = 0; mt < 2; mt++) {
        int m0 = bm + wm + mt * 16 + g, m1 = m0 + 8;
#pragma unroll
        for (int nt = 0; nt < 8; nt++) {
            int n = bn + wn + nt * 8 + 2 * t;
            float bb0 = bias[n], bb1 = bias[n + 1];
            if (m0 < M)
                *(float2*)(C + (size_t)m0 * DIMC + n) =
                    make_float2(acc[mt][nt][0] + bb0, acc[mt][nt][1] + bb1);
            if (m1 < M)
                *(float2*)(C + (size_t)m1 * DIMC + n) =
                    make_float2(acc[mt][nt][2] + bb0, acc[mt][nt][3] + bb1);
        }
    }
}

// ---------------------------------------------------------------------------
// RMSNorm + 3-axis causal RoPE (fast enough; unchanged)
// ---------------------------------------------------------------------------
__global__ __launch_bounds__(256) void norm_rope_kernel(
    float* __restrict__ qb, float* __restrict__ kb,
    const float* __restrict__ gq, const float* __restrict__ gk,
    const float* __restrict__ theta,
    const int* __restrict__ p_gh, const int* __restrict__ p_gw,
    const int* __restrict__ p_cs)
{
    __shared__ float row[DIMC];
    __shared__ float red[256];

    int srow = blockIdx.x;
    int which = blockIdx.y;
    float* buf = which ? kb : qb;
    const float* g = which ? gk : gq;
    float* rptr = buf + (size_t)srow * DIMC;

    int tid = threadIdx.x;
    float vals[6];
    float ss = 0.0f;
#pragma unroll
    for (int q = 0; q < 6; q++) {
        int d = tid + q * 256;
        float v = rptr[d];
        vals[q] = v;
        ss += v * v;
    }
    red[tid] = ss;
    __syncthreads();
    for (int o = 128; o > 0; o >>= 1) {
        if (tid < o) red[tid] += red[tid + o];
        __syncthreads();
    }
    float scale = rsqrtf(red[0] * (1.0f / DIMC) + 1e-6f);
#pragma unroll
    for (int q = 0; q < 6; q++) {
        int d = tid + q * 256;
        row[d] = vals[q] * scale * g[d];
    }
    __syncthreads();

    int gh = *p_gh, gw = *p_gw, cs = *p_cs;
    int fs = gh * gw;
    int sf = cs / fs;
    int f = srow / fs;
    int rem = srow - f * fs;
    int h = rem / gw;
    int w = rem - h * gw;

    for (int p = tid; p < NHEADS * (HD / 2); p += 256) {
        int head = p >> 6;
        int i = p & 63;
        int trow = (i < 22) ? (sf + f) : ((i < 43) ? h : w);
        float ang = theta[trow * (HD / 2) + i];
        float sn, cn;
        __sincosf(ang, &sn, &cn);
        int d0 = head * HD + 2 * i;
        float xr = row[d0], xi = row[d0 + 1];
        rptr[d0]     = xr * cn - xi * sn;
        rptr[d0 + 1] = xr * sn + xi * cn;
    }
}

// ---------------------------------------------------------------------------
// Flash attention, tf32 tensor cores. BM=64 queries, BN=64 keys, 128 threads.
// Warp w owns query rows [w*16, w*16+16). Q frags in regs (pre-scaled).
// Ks stride 132, Vs stride 136, Ps stride 68: all frag loads conflict-free.
// ---------------------------------------------------------------------------
__global__ __launch_bounds__(128) void flash_tc_kernel(
    const float* __restrict__ qbuf, const float* __restrict__ kbuf,
    const float* __restrict__ vbuf, const float* __restrict__ cache_k,
    const float* __restrict__ cache_v, float* __restrict__ obuf, int S,
    const int* __restrict__ p_cs, const int* __restrict__ p_ge,
    const int* __restrict__ p_le)
{
    extern __shared__ float sm[];
    float* Ks = sm;            // 64 * 132
    float* Vs = sm + 8448;     // 64 * 136
    float* Ps = sm + 17152;    // 64 * 68

    int cs = *p_cs, ge = *p_ge, le = *p_le;
    int local_end = le + cs + S - ge;
    int local_start = local_end - S;
    int win_start = local_end - MAX_ATTN_W;
    if (win_start < 0) win_start = 0;
    int L = local_end - win_start;

    int hh = blockIdx.y;
    int qbase = blockIdx.x * 64;
    int tid = threadIdx.x, warp = tid >> 5, lane = tid & 31;
    int g = lane >> 2, t = lane & 3;
    const float scale = 0.08838834764831845f;  // 1/sqrt(128)

    // Q fragments (rows warp*16+g, +8), pre-scaled, tf32
    unsigned qa[16][4];
    {
        int r0 = qbase + warp * 16 + g, r1 = r0 + 8;
        const float* q0p = qbuf + (size_t)r0 * DIMC + hh * HD;
        const float* q1p = qbuf + (size_t)r1 * DIMC + hh * HD;
        bool v0 = r0 < S, v1 = r1 < S;
#pragma unroll
        for (int ks = 0; ks < 16; ks++) {
            int c = ks * 8 + t;
            qa[ks][0] = v0 ? f2tf(q0p[c] * scale) : 0u;
            qa[ks][1] = v1 ? f2tf(q1p[c] * scale) : 0u;
            qa[ks][2] = v0 ? f2tf(q0p[c + 4] * scale) : 0u;
            qa[ks][3] = v1 ? f2tf(q1p[c + 4] * scale) : 0u;
        }
    }

    float oacc[16][4];
#pragma unroll
    for (int nt = 0; nt < 16; nt++)
#pragma unroll
        for (int i = 0; i < 4; i++) oacc[nt][i] = 0.0f;
    float m0s = -1e30f, m1s = -1e30f, l0s = 0.0f, l1s = 0.0f;

    int prow0 = (warp * 16 + g) * 68, prow1 = (warp * 16 + g + 8) * 68;
    int nkt = (L + 63) >> 6;

    for (int kt = 0; kt < nkt; kt++) {
        __syncthreads();
        // load K, V tiles
#pragma unroll
        for (int i = 0; i < 16; i++) {
            int idx = tid + i * 128;
            int r = idx >> 5, c4 = idx & 31;
            int jg = win_start + kt * 64 + r;
            float4 kv = make_float4(0.f, 0.f, 0.f, 0.f), vv = kv;
            if (jg < local_end) {
                const float *ksrc, *vsrc;
                if (jg < local_start) {
                    size_t o = ((size_t)jg * NHEADS + hh) * HD + c4 * 4;
                    ksrc = cache_k + o; vsrc = cache_v + o;
                } else {
                    size_t o = (size_t)(jg - local_start) * DIMC + hh * HD + c4 * 4;
                    ksrc = kbuf + o; vsrc = vbuf + o;
                }
                kv = *(const float4*)ksrc;
                vv = *(const float4*)vsrc;
            }
            kv.x = f2tff(kv.x); kv.y = f2tff(kv.y); kv.z = f2tff(kv.z); kv.w = f2tff(kv.w);
            vv.x = f2tff(vv.x); vv.y = f2tff(vv.y); vv.z = f2tff(vv.z); vv.w = f2tff(vv.w);
            *(float4*)(Ks + r * 132 + c4 * 4) = kv;
            *(float4*)(Vs + r * 136 + c4 * 4) = vv;
        }
        __syncthreads();

        // S = Q K^T
        float sacc[8][4];
#pragma unroll
        for (int nt = 0; nt < 8; nt++)
#pragma unroll
            for (int i = 0; i < 4; i++) sacc[nt][i] = 0.0f;
#pragma unroll
        for (int ks = 0; ks < 16; ks++) {
            int d0 = ks * 8 + t;
#pragma unroll
            for (int nt = 0; nt < 8; nt++) {
                int key = nt * 8 + g;
                unsigned b0 = __float_as_uint(Ks[key * 132 + d0]);
                unsigned b1 = __float_as_uint(Ks[key * 132 + d0 + 4]);
                mma_tf32(sacc[nt], qa[ks], b0, b1);
            }
        }

        // mask + row max
        int colb = kt * 64 + 2 * t;
        float rmax0 = -1e30f, rmax1 = -1e30f;
#pragma unroll
        for (int nt = 0; nt < 8; nt++) {
            int c = colb + nt * 8;
            if (c >= L)     { sacc[nt][0] = -1e30f; sacc[nt][2] = -1e30f; }
            if (c + 1 >= L) { sacc[nt][1] = -1e30f; sacc[nt][3] = -1e30f; }
            rmax0 = fmaxf(rmax0, fmaxf(sacc[nt][0], sacc[nt][1]));
            rmax1 = fmaxf(rmax1, fmaxf(sacc[nt][2], sacc[nt][3]));
        }
        rmax0 = fmaxf(rmax0, __shfl_xor_sync(0xffffffffu, rmax0, 1));
        rmax0 = fmaxf(rmax0, __shfl_xor_sync(0xffffffffu, rmax0, 2));
        rmax1 = fmaxf(rmax1, __shfl_xor_sync(0xffffffffu, rmax1, 1));
        rmax1 = fmaxf(rmax1, __shfl_xor_sync(0xffffffffu, rmax1, 2));
        float newm0 = fmaxf(m0s, rmax0), newm1 = fmaxf(m1s, rmax1);
        float fac0 = __expf(m0s - newm0), fac1 = __expf(m1s - newm1);
        m0s = newm0; m1s = newm1;

        // P = exp(S - m), store to smem (tf32-rounded), accumulate sums
        float rs0 = 0.0f, rs1 = 0.0f;
#pragma unroll
        for (int nt = 0; nt < 8; nt++) {
            float p0 = __expf(sacc[nt][0] - newm0);
            float p1 = __expf(sacc[nt][1] - newm0);
            float p2 = __expf(sacc[nt][2] - newm1);
            float p3 = __expf(sacc[nt][3] - newm1);
            rs0 += p0 + p1; rs1 += p2 + p3;
            int cn = nt * 8 + 2 * t;
            *(float2*)(Ps + prow0 + cn) = make_float2(f2tff(p0), f2tff(p1));
            *(float2*)(Ps + prow1 + cn) = make_float2(f2tff(p2), f2tff(p3));
        }
        rs0 += __shfl_xor_sync(0xffffffffu, rs0, 1);
        rs0 += __shfl_xor_sync(0xffffffffu, rs0, 2);
        rs1 += __shfl_xor_sync(0xffffffffu, rs1, 1);
        rs1 += __shfl_xor_sync(0xffffffffu, rs1, 2);
        l0s = l0s * fac0 + rs0;
        l1s = l1s * fac1 + rs1;
#pragma unroll
        for (int nt = 0; nt < 16; nt++) {
            oacc[nt][0] *= fac0; oacc[nt][1] *= fac0;
            oacc[nt][2] *= fac1; oacc[nt][3] *= fac1;
        }
        __syncwarp();  // P rows are warp-private; cross-lane visibility only

        // O += P V
#pragma unroll
        for (int kk = 0; kk < 8; kk++) {
            int k0 = kk * 8 + t;
            unsigned pa[4];
            pa[0] = __float_as_uint(Ps[prow0 + k0]);
            pa[1] = __float_as_uint(Ps[prow1 + k0]);
            pa[2] = __float_as_uint(Ps[prow0 + k0 + 4]);
            pa[3] = __float_as_uint(Ps[prow1 + k0 + 4]);
            const float* v0r = Vs + k0 * 136 + g;
            const float* v1r = Vs + (k0 + 4) * 136 + g;
#pragma unroll
            for (int nt = 0; nt < 16; nt++) {
                unsigned b0 = __float_as_uint(v0r[nt * 8]);
                unsigned b1 = __float_as_uint(v1r[nt * 8]);
                mma_tf32(oacc[nt], pa, b0, b1);
            }
        }
    }

    // epilogue
    float inv0 = 1.0f / l0s, inv1 = 1.0f / l1s;
    int r0 = qbase + warp * 16 + g, r1 = r0 + 8;
#pragma unroll
    for (int nt = 0; nt < 16; nt++) {
        int d = hh * HD + nt * 8 + 2 * t;
        if (r0 < S)
            *(float2*)(obuf + (size_t)r0 * DIMC + d) =
                make_float2(oacc[nt][0] * inv0, oacc[nt][1] * inv0);
        if (r1 < S)
            *(float2*)(obuf + (size_t)r1 * DIMC + d) =
                make_float2(oacc[nt][2] * inv1, oacc[nt][3] * inv1);
    }
}

// ---------------------------------------------------------------------------
extern "C" void kernel_launch(void* const* d_in, const int* in_sizes, int n_in,
                              void* d_out, int out_size)
{
    const float* x   = (const float*)d_in[0];
    const float* th  = (const float*)d_in[1];
    const float* ck  = (const float*)d_in[2];
    const float* cv  = (const float*)d_in[3];
    const float* wq  = (const float*)d_in[4];
    const float* bq  = (const float*)d_in[5];
    const float* wk  = (const float*)d_in[6];
    const float* bk  = (const float*)d_in[7];
    const float* wv  = (const float*)d_in[8];
    const float* bv  = (const float*)d_in[9];
    const float* wo  = (const float*)d_in[10];
    const float* bo  = (const float*)d_in[11];
    const float* gq  = (const float*)d_in[12];
    const float* gk  = (const float*)d_in[13];
    const int* p_gh  = (const int*)d_in[15];
    const int* p_gw  = (const int*)d_in[16];
    const int* p_cs  = (const int*)d_in[17];
    const int* p_ge  = (const int*)d_in[18];
    const int* p_le  = (const int*)d_in[19];
    float* out = (float*)d_out;

    int S = in_sizes[0] / DIMC;

    float *qp, *kp, *vp, *op;
    cudaGetSymbolAddress((void**)&qp, g_q);
    cudaGetSymbolAddress((void**)&kp, g_k);
    cudaGetSymbolAddress((void**)&vp, g_v);
    cudaGetSymbolAddress((void**)&op, g_o);

    dim3 gg((S + 127) / 128, DIMC / 128);

    gemm_tc_kernel<<<gg, 256>>>(x, wq, bq, qp, S);
    gemm_tc_kernel<<<gg, 256>>>(x, wk, bk, kp, S);
    gemm_tc_kernel<<<gg, 256>>>(x, wv, bv, vp, S);

    norm_rope_kernel<<<dim3(S, 2), 256>>>(qp, kp, gq, gk, th, p_gh, p_gw, p_cs);

    size_t smem = (size_t)(8448 + 8704 + 4352) * sizeof(float);  // 86016 B
    cudaFuncSetAttribute(flash_tc_kernel, cudaFuncAttributeMaxDynamicSharedMemorySize,
                         (int)smem);
    flash_tc_kernel<<<dim3((S + 63) / 64, NHEADS), 128, smem>>>(
        qp, kp, vp, ck, cv, op, S, p_cs, p_ge, p_le);

    gemm_tc_kernel<<<gg, 256>>>(op, wo, bo, out, S);
}

// round 5
// speedup vs baseline: 4.0848x; 1.9135x over previous
#include <cuda_runtime.h>
#include <math.h>

#define DIMC 1536
#define NHEADS 12
#define HD 128
#define MAX_ATTN_W 5632
#define MAXS 3200
#define PADW 5632   // padded window rows (88 tiles of 64)

__device__ float g_q[MAXS * DIMC];
__device__ float g_k[MAXS * DIMC];
__device__ float g_v[MAXS * DIMC];
__device__ float g_o[MAXS * DIMC];
__device__ float g_xr[MAXS * DIMC];                 // tf32-rounded x
__device__ float g_wr[4 * DIMC * DIMC];             // rounded wq,wk,wv,wo
__device__ float g_kw[NHEADS * PADW * HD];          // packed rounded K window
__device__ float g_vw[NHEADS * PADW * HD];          // packed rounded V window

__device__ __forceinline__ unsigned f2tf(float x) {
    unsigned u; asm("cvt.rna.tf32.f32 %0, %1;" : "=r"(u) : "f"(x)); return u;
}
__device__ __forceinline__ float f2tff(float x) { return __uint_as_float(f2tf(x)); }

__device__ __forceinline__ void mma_tf32(float* d, const unsigned* a,
                                         unsigned b0, unsigned b1) {
    asm volatile(
        "mma.sync.aligned.m16n8k8.row.col.f32.tf32.tf32.f32 "
        "{%0,%1,%2,%3}, {%4,%5,%6,%7}, {%8,%9}, {%0,%1,%2,%3};\n"
        : "+f"(d[0]), "+f"(d[1]), "+f"(d[2]), "+f"(d[3])
        : "r"(a[0]), "r"(a[1]), "r"(a[2]), "r"(a[3]), "r"(b0), "r"(b1));
}

__device__ __forceinline__ void cpa16(float* dst_smem, const float* src) {
    unsigned d = (unsigned)__cvta_generic_to_shared(dst_smem);
    asm volatile("cp.async.cg.shared.global [%0], [%1], 16;\n" :: "r"(d), "l"(src));
}
#define CP_COMMIT() asm volatile("cp.async.commit_group;\n" ::: "memory")
#define CP_WAIT(n)  asm volatile("cp.async.wait_group " #n ";\n" ::: "memory")

// ---------------------------------------------------------------------------
// prep: round n floats to tf32
// ---------------------------------------------------------------------------
__global__ __launch_bounds__(256) void prep_round_kernel(
    const float* __restrict__ src, float* __restrict__ dst, int n4)
{
    int i = blockIdx.x * 256 + threadIdx.x;
    if (i < n4) {
        float4 v = ((const float4*)src)[i];
        v.x = f2tff(v.x); v.y = f2tff(v.y); v.z = f2tff(v.z); v.w = f2tff(v.w);
        ((float4*)dst)[i] = v;
    }
}

// ---------------------------------------------------------------------------
// prep: pack + round KV window into per-head contiguous buffers (zero pad)
// ---------------------------------------------------------------------------
__global__ __launch_bounds__(256) void prep_kv_kernel(
    const float* __restrict__ kbuf, const float* __restrict__ vbuf,
    const float* __restrict__ cache_k, const float* __restrict__ cache_v, int S,
    const int* __restrict__ p_cs, const int* __restrict__ p_ge,
    const int* __restrict__ p_le)
{
    int cs = *p_cs, ge = *p_ge, le = *p_le;
    int local_end = le + cs + S - ge;
    int local_start = local_end - S;
    int win_start = local_end - MAX_ATTN_W;
    if (win_start < 0) win_start = 0;
    int L = local_end - win_start;

    int idx = blockIdx.x * 256 + threadIdx.x;        // f4 index
    int total = NHEADS * PADW * (HD / 4);
    if (idx >= total) return;
    int c4 = idx & 31;
    int j = (idx >> 5) % PADW;
    int h = idx / (PADW * 32);

    float4 kv = make_float4(0.f, 0.f, 0.f, 0.f), vv = kv;
    if (j < L) {
        int jg = win_start + j;
        const float *ks, *vs;
        if (jg < local_start) {
            size_t o = ((size_t)jg * NHEADS + h) * HD + c4 * 4;
            ks = cache_k + o; vs = cache_v + o;
        } else {
            size_t o = (size_t)(jg - local_start) * DIMC + h * HD + c4 * 4;
            ks = kbuf + o; vs = vbuf + o;
        }
        kv = *(const float4*)ks; vv = *(const float4*)vs;
        kv.x = f2tff(kv.x); kv.y = f2tff(kv.y); kv.z = f2tff(kv.z); kv.w = f2tff(kv.w);
        vv.x = f2tff(vv.x); vv.y = f2tff(vv.y); vv.z = f2tff(vv.z); vv.w = f2tff(vv.w);
    }
    ((float4*)g_kw)[idx] = kv;
    ((float4*)g_vw)[idx] = vv;
}

// ---------------------------------------------------------------------------
// GEMM: C[M,1536] = A @ W^T + bias. Inputs pre-rounded to tf32.
// BM=BN=128, BK=16, 256 thr, double-buffered cp.async. z selects {q,k,v}.
// ---------------------------------------------------------------------------
__global__ __launch_bounds__(256) void gemm_tc_kernel(
    const float* __restrict__ A, const float* __restrict__ Wbase,
    const float* __restrict__ b0p, const float* __restrict__ b1p,
    const float* __restrict__ b2p, float* __restrict__ C0,
    float* __restrict__ C1, float* __restrict__ C2, int M, int nw)
{
    extern __shared__ float smg[];
    // layout: As0 As1 Bs0 Bs1, each 128*20
    int z = blockIdx.z;
    const float* W = Wbase + (size_t)z * DIMC * DIMC;
    const float* bias = (z == 0) ? b0p : (z == 1) ? b1p : b2p;
    float* C = (z == 0) ? C0 : (z == 1) ? C1 : C2;

    int tid = threadIdx.x, warp = tid >> 5, lane = tid & 31;
    int g = lane >> 2, t = lane & 3;
    int wm = (warp & 3) * 32, wn = (warp >> 2) * 64;
    int bm = blockIdx.x * 128, bn = blockIdx.y * 128;

    float acc[2][8][4];
#pragma unroll
    for (int mt = 0; mt < 2; mt++)
#pragma unroll
        for (int nt = 0; nt < 8; nt++)
#pragma unroll
            for (int i = 0; i < 4; i++) acc[mt][nt][i] = 0.0f;

#define GFILL(stg, kt)                                                        \
    {                                                                         \
        float* As_ = smg + (stg) * 2560;                                      \
        float* Bs_ = smg + 5120 + (stg) * 2560;                               \
        _Pragma("unroll")                                                     \
        for (int j = 0; j < 2; j++) {                                         \
            int idx = tid + j * 256;                                          \
            int row = idx >> 2, c4 = idx & 3;                                 \
            cpa16(As_ + row * 20 + c4 * 4,                                    \
                  A + (size_t)(bm + row) * DIMC + (kt) * 16 + c4 * 4);        \
            cpa16(Bs_ + row * 20 + c4 * 4,                                    \
                  W + (size_t)(bn + row) * DIMC + (kt) * 16 + c4 * 4);        \
        }                                                                     \
    }

    GFILL(0, 0); CP_COMMIT();
    for (int kt = 0; kt < DIMC / 16; kt++) {
        int s = kt & 1;
        if (kt + 1 < DIMC / 16) { GFILL(s ^ 1, kt + 1); CP_COMMIT(); CP_WAIT(1); }
        else CP_WAIT(0);
        __syncthreads();
        const float* As = smg + s * 2560;
        const float* Bs = smg + 5120 + s * 2560;
#pragma unroll
        for (int kst = 0; kst < 2; kst++) {
            int k0 = kst * 8 + t;
            unsigned af[2][4];
#pragma unroll
            for (int mt = 0; mt < 2; mt++) {
                int m0 = wm + mt * 16 + g;
                af[mt][0] = __float_as_uint(As[m0 * 20 + k0]);
                af[mt][1] = __float_as_uint(As[(m0 + 8) * 20 + k0]);
                af[mt][2] = __float_as_uint(As[m0 * 20 + k0 + 4]);
                af[mt][3] = __float_as_uint(As[(m0 + 8) * 20 + k0 + 4]);
            }
#pragma unroll
            for (int nt = 0; nt < 8; nt++) {
                int n = wn + nt * 8 + g;
                unsigned bf0 = __float_as_uint(Bs[n * 20 + k0]);
                unsigned bf1 = __float_as_uint(Bs[n * 20 + k0 + 4]);
                mma_tf32(acc[0][nt], af[0], bf0, bf1);
                mma_tf32(acc[1][nt], af[1], bf0, bf1);
            }
        }
        __syncthreads();
    }
#pragma unroll
    for (int mt = 0; mt < 2; mt++) {
        int m0 = bm + wm + mt * 16 + g, m1 = m0 + 8;
#pragma unroll
        for (int nt = 0; nt < 8; nt++) {
            int n = bn + wn + nt * 8 + 2 * t;
            float bb0 = bias[n], bb1 = bias[n + 1];
            if (m0 < M)
                *(float2*)(C + (size_t)m0 * DIMC + n) =
                    make_float2(acc[mt][nt][0] + bb0, acc[mt][nt][1] + bb1);
            if (m1 < M)
                *(float2*)(C + (size_t)m1 * DIMC + n) =
                    make_float2(acc[mt][nt][2] + bb0, acc[mt][nt][3] + bb1);
        }
    }
}

// ---------------------------------------------------------------------------
// RMSNorm + 3-axis causal RoPE (unchanged)
// ---------------------------------------------------------------------------
__global__ __launch_bounds__(256) void norm_rope_kernel(
    float* __restrict__ qb, float* __restrict__ kb,
    const float* __restrict__ gq, const float* __restrict__ gk,
    const float* __restrict__ theta,
    const int* __restrict__ p_gh, const int* __restrict__ p_gw,
    const int* __restrict__ p_cs)
{
    __shared__ float row[DIMC];
    __shared__ float red[256];

    int srow = blockIdx.x;
    int which = blockIdx.y;
    float* buf = which ? kb : qb;
    const float* g = which ? gk : gq;
    float* rptr = buf + (size_t)srow * DIMC;

    int tid = threadIdx.x;
    float vals[6];
    float ss = 0.0f;
#pragma unroll
    for (int q = 0; q < 6; q++) {
        int d = tid + q * 256;
        float v = rptr[d];
        vals[q] = v;
        ss += v * v;
    }
    red[tid] = ss;
    __syncthreads();
    for (int o = 128; o > 0; o >>= 1) {
        if (tid < o) red[tid] += red[tid + o];
        __syncthreads();
    }
    float scale = rsqrtf(red[0] * (1.0f / DIMC) + 1e-6f);
#pragma unroll
    for (int q = 0; q < 6; q++) {
        int d = tid + q * 256;
        row[d] = vals[q] * scale * g[d];
    }
    __syncthreads();

    int gh = *p_gh, gw = *p_gw, cs = *p_cs;
    int fs = gh * gw;
    int sf = cs / fs;
    int f = srow / fs;
    int rem = srow - f * fs;
    int h = rem / gw;
    int w = rem - h * gw;

    for (int p = tid; p < NHEADS * (HD / 2); p += 256) {
        int head = p >> 6;
        int i = p & 63;
        int trow = (i < 22) ? (sf + f) : ((i < 43) ? h : w);
        float ang = theta[trow * (HD / 2) + i];
        float sn, cn;
        __sincosf(ang, &sn, &cn);
        int d0 = head * HD + 2 * i;
        float xr = row[d0], xi = row[d0 + 1];
        rptr[d0]     = xr * cn - xi * sn;
        rptr[d0 + 1] = xr * sn + xi * cn;
    }
}

// ---------------------------------------------------------------------------
// Flash attention, tf32 MMA, BM=128 (8 warps x 16 rows), BN=64.
// K/V double-buffered cp.async from pre-packed g_kw/g_vw.
// smem: [Ks0|Vs0|Ks1|Vs1|Ps], strides 132/136/68 (conflict-free frags).
// ---------------------------------------------------------------------------
__global__ __launch_bounds__(256) void flash_tc_kernel(
    const float* __restrict__ qbuf, float* __restrict__ obuf, int S,
    const int* __restrict__ p_cs, const int* __restrict__ p_ge,
    const int* __restrict__ p_le)
{
    extern __shared__ float sm[];
    // stage stride 17152 floats (Ks 8448 + Vs 8704); Ps at 34304
    float* Ps = sm + 34304;

    int cs = *p_cs, ge = *p_ge, le = *p_le;
    int local_end = le + cs + S - ge;
    int win_start = local_end - MAX_ATTN_W;
    if (win_start < 0) win_start = 0;
    int L = local_end - win_start;

    int hh = blockIdx.y;
    int qbase = blockIdx.x * 128;
    int tid = threadIdx.x, warp = tid >> 5, lane = tid & 31;
    int g = lane >> 2, t = lane & 3;
    const float scale = 0.08838834764831845f;

    // Q fragments in registers, pre-scaled + rounded
    unsigned qa[16][4];
    {
        int r0 = qbase + warp * 16 + g, r1 = r0 + 8;
        const float* q0p = qbuf + (size_t)r0 * DIMC + hh * HD;
        const float* q1p = qbuf + (size_t)r1 * DIMC + hh * HD;
        bool v0 = r0 < S, v1 = r1 < S;
#pragma unroll
        for (int ks = 0; ks < 16; ks++) {
            int c = ks * 8 + t;
            qa[ks][0] = v0 ? f2tf(q0p[c] * scale) : 0u;
            qa[ks][1] = v1 ? f2tf(q1p[c] * scale) : 0u;
            qa[ks][2] = v0 ? f2tf(q0p[c + 4] * scale) : 0u;
            qa[ks][3] = v1 ? f2tf(q1p[c + 4] * scale) : 0u;
        }
    }

    float oacc[16][4];
#pragma unroll
    for (int nt = 0; nt < 16; nt++)
#pragma unroll
        for (int i = 0; i < 4; i++) oacc[nt][i] = 0.0f;
    float m0s = -1e30f, m1s = -1e30f, l0s = 0.0f, l1s = 0.0f;

    int prow0 = (warp * 16 + g) * 68, prow1 = prow0 + 8 * 68;
    int nkt = (L + 63) >> 6;

    const float* kwb = g_kw + (size_t)hh * PADW * HD;
    const float* vwb = g_vw + (size_t)hh * PADW * HD;

#define KVFILL(stg, kt)                                                       \
    {                                                                         \
        float* Ks_ = sm + (stg) * 17152;                                      \
        float* Vs_ = Ks_ + 8448;                                              \
        const float* kb_ = kwb + (size_t)(kt) * 64 * HD;                      \
        const float* vb_ = vwb + (size_t)(kt) * 64 * HD;                      \
        _Pragma("unroll")                                                     \
        for (int j = 0; j < 8; j++) {                                         \
            int idx = tid + j * 256;                                          \
            int row = idx >> 5, c4 = idx & 31;                                \
            cpa16(Ks_ + row * 132 + c4 * 4, kb_ + row * HD + c4 * 4);         \
            cpa16(Vs_ + row * 136 + c4 * 4, vb_ + row * HD + c4 * 4);         \
        }                                                                     \
    }

    KVFILL(0, 0); CP_COMMIT();
    for (int kt = 0; kt < nkt; kt++) {
        int s = kt & 1;
        if (kt + 1 < nkt) { KVFILL(s ^ 1, kt + 1); CP_COMMIT(); CP_WAIT(1); }
        else CP_WAIT(0);
        __syncthreads();
        const float* Ks = sm + s * 17152;
        const float* Vs = Ks + 8448;

        // S = Q K^T
        float sacc[8][4];
#pragma unroll
        for (int nt = 0; nt < 8; nt++)
#pragma unroll
            for (int i = 0; i < 4; i++) sacc[nt][i] = 0.0f;
#pragma unroll
        for (int ks = 0; ks < 16; ks++) {
            int d0 = ks * 8 + t;
#pragma unroll
            for (int nt = 0; nt < 8; nt++) {
                int key = nt * 8 + g;
                unsigned b0 = __float_as_uint(Ks[key * 132 + d0]);
                unsigned b1 = __float_as_uint(Ks[key * 132 + d0 + 4]);
                mma_tf32(sacc[nt], qa[ks], b0, b1);
            }
        }

        // mask + row max
        int colb = kt * 64 + 2 * t;
        float rmax0 = -1e30f, rmax1 = -1e30f;
#pragma unroll
        for (int nt = 0; nt < 8; nt++) {
            int c = colb + nt * 8;
            if (c >= L)     { sacc[nt][0] = -1e30f; sacc[nt][2] = -1e30f; }
            if (c + 1 >= L) { sacc[nt][1] = -1e30f; sacc[nt][3] = -1e30f; }
            rmax0 = fmaxf(rmax0, fmaxf(sacc[nt][0], sacc[nt][1]));
            rmax1 = fmaxf(rmax1, fmaxf(sacc[nt][2], sacc[nt][3]));
        }
        rmax0 = fmaxf(rmax0, __shfl_xor_sync(0xffffffffu, rmax0, 1));
        rmax0 = fmaxf(rmax0, __shfl_xor_sync(0xffffffffu, rmax0, 2));
        rmax1 = fmaxf(rmax1, __shfl_xor_sync(0xffffffffu, rmax1, 1));
        rmax1 = fmaxf(rmax1, __shfl_xor_sync(0xffffffffu, rmax1, 2));
        float newm0 = fmaxf(m0s, rmax0), newm1 = fmaxf(m1s, rmax1);
        float fac0 = __expf(m0s - newm0), fac1 = __expf(m1s - newm1);
        m0s = newm0; m1s = newm1;

        float rs0 = 0.0f, rs1 = 0.0f;
#pragma unroll
        for (int nt = 0; nt < 8; nt++) {
            float p0 = __expf(sacc[nt][0] - newm0);
            float p1 = __expf(sacc[nt][1] - newm0);
            float p2 = __expf(sacc[nt][2] - newm1);
            float p3 = __expf(sacc[nt][3] - newm1);
            rs0 += p0 + p1; rs1 += p2 + p3;
            int cn = nt * 8 + 2 * t;
            *(float2*)(Ps + prow0 + cn) = make_float2(f2tff(p0), f2tff(p1));
            *(float2*)(Ps + prow1 + cn) = make_float2(f2tff(p2), f2tff(p3));
        }
        rs0 += __shfl_xor_sync(0xffffffffu, rs0, 1);
        rs0 += __shfl_xor_sync(0xffffffffu, rs0, 2);
        rs1 += __shfl_xor_sync(0xffffffffu, rs1, 1);
        rs1 += __shfl_xor_sync(0xffffffffu, rs1, 2);
        l0s = l0s * fac0 + rs0;
        l1s = l1s * fac1 + rs1;
#pragma unroll
        for (int nt = 0; nt < 16; nt++) {
            oacc[nt][0] *= fac0; oacc[nt][1] *= fac0;
            oacc[nt][2] *= fac1; oacc[nt][3] *= fac1;
        }
        __syncwarp();  // P rows warp-private

        // O += P V
#pragma unroll
        for (int kk = 0; kk < 8; kk++) {
            int k0 = kk * 8 + t;
            unsigned pa[4];
            pa[0] = __float_as_uint(Ps[prow0 + k0]);
            pa[1] = __float_as_uint(Ps[prow1 + k0]);
            pa[2] = __float_as_uint(Ps[prow0 + k0 + 4]);
            pa[3] = __float_as_uint(Ps[prow1 + k0 + 4]);
            const float* v0r = Vs + k0 * 136 + g;
            const float* v1r = v0r + 4 * 136;
#pragma unroll
            for (int nt = 0; nt < 16; nt++) {
                unsigned b0 = __float_as_uint(v0r[nt * 8]);
                unsigned b1 = __float_as_uint(v1r[nt * 8]);
                mma_tf32(oacc[nt], pa, b0, b1);
            }
        }
        __syncthreads();
    }

    // epilogue (rounded, so out-GEMM needs no cvt)
    float inv0 = 1.0f / l0s, inv1 = 1.0f / l1s;
    int r0 = qbase + warp * 16 + g, r1 = r0 + 8;
#pragma unroll
    for (int nt = 0; nt < 16; nt++) {
        int d = hh * HD + nt * 8 + 2 * t;
        if (r0 < S)
            *(float2*)(obuf + (size_t)r0 * DIMC + d) =
                make_float2(f2tff(oacc[nt][0] * inv0), f2tff(oacc[nt][1] * inv0));
        if (r1 < S)
            *(float2*)(obuf + (size_t)r1 * DIMC + d) =
                make_float2(f2tff(oacc[nt][2] * inv1), f2tff(oacc[nt][3] * inv1));
    }
}

// ---------------------------------------------------------------------------
extern "C" void kernel_launch(void* const* d_in, const int* in_sizes, int n_in,
                              void* d_out, int out_size)
{
    const float* x   = (const float*)d_in[0];
    const float* th  = (const float*)d_in[1];
    const float* ck  = (const float*)d_in[2];
    const float* cv  = (const float*)d_in[3];
    const float* wq  = (const float*)d_in[4];
    const float* bq  = (const float*)d_in[5];
    const float* wk  = (const float*)d_in[6];
    const float* bk  = (const float*)d_in[7];
    const float* wv  = (const float*)d_in[8];
    const float* bv  = (const float*)d_in[9];
    const float* wo  = (const float*)d_in[10];
    const float* bo  = (const float*)d_in[11];
    const float* gq  = (const float*)d_in[12];
    const float* gk  = (const float*)d_in[13];
    const int* p_gh  = (const int*)d_in[15];
    const int* p_gw  = (const int*)d_in[16];
    const int* p_cs  = (const int*)d_in[17];
    const int* p_ge  = (const int*)d_in[18];
    const int* p_le  = (const int*)d_in[19];
    float* out = (float*)d_out;

    int S = in_sizes[0] / DIMC;

    float *qp, *kp, *vp, *op, *xrp, *wrp;
    cudaGetSymbolAddress((void**)&qp, g_q);
    cudaGetSymbolAddress((void**)&kp, g_k);
    cudaGetSymbolAddress((void**)&vp, g_v);
    cudaGetSymbolAddress((void**)&op, g_o);
    cudaGetSymbolAddress((void**)&xrp, g_xr);
    cudaGetSymbolAddress((void**)&wrp, g_wr);

    // --- prep: round weights + x ---
    int wn4 = DIMC * DIMC / 4;
    prep_round_kernel<<<(wn4 + 255) / 256, 256>>>(wq, wrp + 0 * DIMC * DIMC, wn4);
    prep_round_kernel<<<(wn4 + 255) / 256, 256>>>(wk, wrp + 1 * DIMC * DIMC, wn4);
    prep_round_kernel<<<(wn4 + 255) / 256, 256>>>(wv, wrp + 2 * DIMC * DIMC, wn4);
    prep_round_kernel<<<(wn4 + 255) / 256, 256>>>(wo, wrp + 3 * DIMC * DIMC, wn4);
    int xn4 = S * DIMC / 4;
    prep_round_kernel<<<(xn4 + 255) / 256, 256>>>(x, xrp, xn4);

    // --- QKV projections (fused z-grid) ---
    size_t gsm = 10240 * sizeof(float);  // 40KB
    cudaFuncSetAttribute(gemm_tc_kernel, cudaFuncAttributeMaxDynamicSharedMemorySize,
                         (int)gsm);
    dim3 gqkv((S + 127) / 128, DIMC / 128, 3);
    gemm_tc_kernel<<<gqkv, 256, gsm>>>(xrp, wrp, bq, bk, bv, qp, kp, vp, S, 3);

    // --- norm + rope ---
    norm_rope_kernel<<<dim3(S, 2), 256>>>(qp, kp, gq, gk, th, p_gh, p_gw, p_cs);

    // --- pack KV window ---
    int kvn = NHEADS * PADW * (HD / 4);
    prep_kv_kernel<<<(kvn + 255) / 256, 256>>>(kp, vp, ck, cv, S, p_cs, p_ge, p_le);

    // --- flash attention ---
    size_t fsm = (size_t)(34304 + 128 * 68) * sizeof(float);  // 172032 B
    cudaFuncSetAttribute(flash_tc_kernel, cudaFuncAttributeMaxDynamicSharedMemorySize,
                         (int)fsm);
    flash_tc_kernel<<<dim3((S + 127) / 128, NHEADS), 256, fsm>>>(
        qp, op, S, p_cs, p_ge, p_le);

    // --- output projection ---
    dim3 go((S + 127) / 128, DIMC / 128, 1);
    gemm_tc_kernel<<<go, 256, gsm>>>(op, wrp + (size_t)3 * DIMC * DIMC, bo, bo, bo,
                                     out, out, out, S, 1);
}

// round 6
// speedup vs baseline: 4.0856x; 1.0002x over previous
#include <cuda_runtime.h>
#include <math.h>

#define DIMC 1536
#define NHEADS 12
#define HD 128
#define MAX_ATTN_W 5632
#define MAXS 3200
#define PADW 5632   // padded window rows (88 tiles of 64)

__device__ float g_q[MAXS * DIMC];
__device__ float g_k[MAXS * DIMC];
__device__ float g_v[MAXS * DIMC];
__device__ float g_o[MAXS * DIMC];
__device__ float g_xr[MAXS * DIMC];                 // tf32-rounded x
__device__ float g_wr[4 * DIMC * DIMC];             // rounded wq,wk,wv,wo
__device__ float g_kw[NHEADS * PADW * HD];          // packed rounded K window
__device__ float g_vw[NHEADS * PADW * HD];          // packed rounded V window

__device__ __forceinline__ unsigned f2tf(float x) {
    unsigned u; asm("cvt.rna.tf32.f32 %0, %1;" : "=r"(u) : "f"(x)); return u;
}
__device__ __forceinline__ float f2tff(float x) { return __uint_as_float(f2tf(x)); }

__device__ __forceinline__ void mma_tf32(float* d, const unsigned* a,
                                         unsigned b0, unsigned b1) {
    asm volatile(
        "mma.sync.aligned.m16n8k8.row.col.f32.tf32.tf32.f32 "
        "{%0,%1,%2,%3}, {%4,%5,%6,%7}, {%8,%9}, {%0,%1,%2,%3};\n"
        : "+f"(d[0]), "+f"(d[1]), "+f"(d[2]), "+f"(d[3])
        : "r"(a[0]), "r"(a[1]), "r"(a[2]), "r"(a[3]), "r"(b0), "r"(b1));
}

__device__ __forceinline__ void cpa16(float* dst_smem, const float* src) {
    unsigned d = (unsigned)__cvta_generic_to_shared(dst_smem);
    asm volatile("cp.async.cg.shared.global [%0], [%1], 16;\n" :: "r"(d), "l"(src));
}
#define CP_COMMIT() asm volatile("cp.async.commit_group;\n" ::: "memory")
#define CP_WAIT(n)  asm volatile("cp.async.wait_group " #n ";\n" ::: "memory")

// ---------------------------------------------------------------------------
// prep: round n floats to tf32
// ---------------------------------------------------------------------------
__global__ __launch_bounds__(256) void prep_round_kernel(
    const float* __restrict__ src, float* __restrict__ dst, int n4)
{
    int i = blockIdx.x * 256 + threadIdx.x;
    if (i < n4) {
        float4 v = ((const float4*)src)[i];
        v.x = f2tff(v.x); v.y = f2tff(v.y); v.z = f2tff(v.z); v.w = f2tff(v.w);
        ((float4*)dst)[i] = v;
    }
}

// ---------------------------------------------------------------------------
// prep: pack + round KV window into per-head contiguous buffers (zero pad)
// ---------------------------------------------------------------------------
__global__ __launch_bounds__(256) void prep_kv_kernel(
    const float* __restrict__ kbuf, const float* __restrict__ vbuf,
    const float* __restrict__ cache_k, const float* __restrict__ cache_v, int S,
    const int* __restrict__ p_cs, const int* __restrict__ p_ge,
    const int* __restrict__ p_le)
{
    int cs = *p_cs, ge = *p_ge, le = *p_le;
    int local_end = le + cs + S - ge;
    int local_start = local_end - S;
    int win_start = local_end - MAX_ATTN_W;
    if (win_start < 0) win_start = 0;
    int L = local_end - win_start;

    int idx = blockIdx.x * 256 + threadIdx.x;        // f4 index
    int total = NHEADS * PADW * (HD / 4);
    if (idx >= total) return;
    int c4 = idx & 31;
    int j = (idx >> 5) % PADW;
    int h = idx / (PADW * 32);

    float4 kv = make_float4(0.f, 0.f, 0.f, 0.f), vv = kv;
    if (j < L) {
        int jg = win_start + j;
        const float *ks, *vs;
        if (jg < local_start) {
            size_t o = ((size_t)jg * NHEADS + h) * HD + c4 * 4;
            ks = cache_k + o; vs = cache_v + o;
        } else {
            size_t o = (size_t)(jg - local_start) * DIMC + h * HD + c4 * 4;
            ks = kbuf + o; vs = vbuf + o;
        }
        kv = *(const float4*)ks; vv = *(const float4*)vs;
        kv.x = f2tff(kv.x); kv.y = f2tff(kv.y); kv.z = f2tff(kv.z); kv.w = f2tff(kv.w);
        vv.x = f2tff(vv.x); vv.y = f2tff(vv.y); vv.z = f2tff(vv.z); vv.w = f2tff(vv.w);
    }
    ((float4*)g_kw)[idx] = kv;
    ((float4*)g_vw)[idx] = vv;
}

// ---------------------------------------------------------------------------
// GEMM: C[M,1536] = A @ W^T + bias. Inputs pre-rounded to tf32.
// BM=BN=128, BK=16, 256 thr, double-buffered cp.async. z selects {q,k,v}.
// ---------------------------------------------------------------------------
__global__ __launch_bounds__(256) void gemm_tc_kernel(
    const float* __restrict__ A, const float* __restrict__ Wbase,
    const float* __restrict__ b0p, const float* __restrict__ b1p,
    const float* __restrict__ b2p, float* __restrict__ C0,
    float* __restrict__ C1, float* __restrict__ C2, int M, int nw)
{
    extern __shared__ float smg[];
    // layout: As0 As1 Bs0 Bs1, each 128*20
    int z = blockIdx.z;
    const float* W = Wbase + (size_t)z * DIMC * DIMC;
    const float* bias = (z == 0) ? b0p : (z == 1) ? b1p : b2p;
    float* C = (z == 0) ? C0 : (z == 1) ? C1 : C2;

    int tid = threadIdx.x, warp = tid >> 5, lane = tid & 31;
    int g = lane >> 2, t = lane & 3;
    int wm = (warp & 3) * 32, wn = (warp >> 2) * 64;
    int bm = blockIdx.x * 128, bn = blockIdx.y * 128;

    float acc[2][8][4];
#pragma unroll
    for (int mt = 0; mt < 2; mt++)
#pragma unroll
        for (int nt = 0; nt < 8; nt++)
#pragma unroll
            for (int i = 0; i < 4; i++) acc[mt][nt][i] = 0.0f;

#define GFILL(stg, kt)                                                        \
    {                                                                         \
        float* As_ = smg + (stg) * 2560;                                      \
        float* Bs_ = smg + 5120 + (stg) * 2560;                               \
        _Pragma("unroll")                                                     \
        for (int j = 0; j < 2; j++) {                                         \
            int idx = tid + j * 256;                                          \
            int row = idx >> 2, c4 = idx & 3;                                 \
            cpa16(As_ + row * 20 + c4 * 4,                                    \
                  A + (size_t)(bm + row) * DIMC + (kt) * 16 + c4 * 4);        \
            cpa16(Bs_ + row * 20 + c4 * 4,                                    \
                  W + (size_t)(bn + row) * DIMC + (kt) * 16 + c4 * 4);        \
        }                                                                     \
    }

    GFILL(0, 0); CP_COMMIT();
    for (int kt = 0; kt < DIMC / 16; kt++) {
        int s = kt & 1;
        if (kt + 1 < DIMC / 16) { GFILL(s ^ 1, kt + 1); CP_COMMIT(); CP_WAIT(1); }
        else CP_WAIT(0);
        __syncthreads();
        const float* As = smg + s * 2560;
        const float* Bs = smg + 5120 + s * 2560;
#pragma unroll
        for (int kst = 0; kst < 2; kst++) {
            int k0 = kst * 8 + t;
            unsigned af[2][4];
#pragma unroll
            for (int mt = 0; mt < 2; mt++) {
                int m0 = wm + mt * 16 + g;
                af[mt][0] = __float_as_uint(As[m0 * 20 + k0]);
                af[mt][1] = __float_as_uint(As[(m0 + 8) * 20 + k0]);
                af[mt][2] = __float_as_uint(As[m0 * 20 + k0 + 4]);
                af[mt][3] = __float_as_uint(As[(m0 + 8) * 20 + k0 + 4]);
            }
#pragma unroll
            for (int nt = 0; nt < 8; nt++) {
                int n = wn + nt * 8 + g;
                unsigned bf0 = __float_as_uint(Bs[n * 20 + k0]);
                unsigned bf1 = __float_as_uint(Bs[n * 20 + k0 + 4]);
                mma_tf32(acc[0][nt], af[0], bf0, bf1);
                mma_tf32(acc[1][nt], af[1], bf0, bf1);
            }
        }
        __syncthreads();
    }
#pragma unroll
    for (int mt = 0; mt < 2; mt++) {
        int m0 = bm + wm + mt * 16 + g, m1 = m0 + 8;
#pragma unroll
        for (int nt = 0; nt < 8; nt++) {
            int n = bn + wn + nt * 8 + 2 * t;
            float bb0 = bias[n], bb1 = bias[n + 1];
            if (m0 < M)
                *(float2*)(C + (size_t)m0 * DIMC + n) =
                    make_float2(acc[mt][nt][0] + bb0, acc[mt][nt][1] + bb1);
            if (m1 < M)
                *(float2*)(C + (size_t)m1 * DIMC + n) =
                    make_float2(acc[mt][nt][2] + bb0, acc[mt][nt][3] + bb1);
        }
    }
}

// ---------------------------------------------------------------------------
// RMSNorm + 3-axis causal RoPE (unchanged)
// ---------------------------------------------------------------------------
__global__ __launch_bounds__(256) void norm_rope_kernel(
    float* __restrict__ qb, float* __restrict__ kb,
    const float* __restrict__ gq, const float* __restrict__ gk,
    const float* __restrict__ theta,
    const int* __restrict__ p_gh, const int* __restrict__ p_gw,
    const int* __restrict__ p_cs)
{
    __shared__ float row[DIMC];
    __shared__ float red[256];

    int srow = blockIdx.x;
    int which = blockIdx.y;
    float* buf = which ? kb : qb;
    const float* g = which ? gk : gq;
    float* rptr = buf + (size_t)srow * DIMC;

    int tid = threadIdx.x;
    float vals[6];
    float ss = 0.0f;
#pragma unroll
    for (int q = 0; q < 6; q++) {
        int d = tid + q * 256;
        float v = rptr[d];
        vals[q] = v;
        ss += v * v;
    }
    red[tid] = ss;
    __syncthreads();
    for (int o = 128; o > 0; o >>= 1) {
        if (tid < o) red[tid] += red[tid + o];
        __syncthreads();
    }
    float scale = rsqrtf(red[0] * (1.0f / DIMC) + 1e-6f);
#pragma unroll
    for (int q = 0; q < 6; q++) {
        int d = tid + q * 256;
        row[d] = vals[q] * scale * g[d];
    }
    __syncthreads();

    int gh = *p_gh, gw = *p_gw, cs = *p_cs;
    int fs = gh * gw;
    int sf = cs / fs;
    int f = srow / fs;
    int rem = srow - f * fs;
    int h = rem / gw;
    int w = rem - h * gw;

    for (int p = tid; p < NHEADS * (HD / 2); p += 256) {
        int head = p >> 6;
        int i = p & 63;
        int trow = (i < 22) ? (sf + f) : ((i < 43) ? h : w);
        float ang = theta[trow * (HD / 2) + i];
        float sn, cn;
        __sincosf(ang, &sn, &cn);
        int d0 = head * HD + 2 * i;
        float xr = row[d0], xi = row[d0 + 1];
        rptr[d0]     = xr * cn - xi * sn;
        rptr[d0 + 1] = xr * sn + xi * cn;
    }
}

// ---------------------------------------------------------------------------
// Flash attention, tf32 MMA, BM=128 (8 warps x 16 rows), BN=64.
// K/V double-buffered cp.async from pre-packed g_kw/g_vw.
// smem: [Ks0|Vs0|Ks1|Vs1|Ps], strides 132/136/68 (conflict-free frags).
// ---------------------------------------------------------------------------
__global__ __launch_bounds__(256) void flash_tc_kernel(
    const float* __restrict__ qbuf, float* __restrict__ obuf, int S,
    const int* __restrict__ p_cs, const int* __restrict__ p_ge,
    const int* __restrict__ p_le)
{
    extern __shared__ float sm[];
    // stage stride 17152 floats (Ks 8448 + Vs 8704); Ps at 34304
    float* Ps = sm + 34304;

    int cs = *p_cs, ge = *p_ge, le = *p_le;
    int local_end = le + cs + S - ge;
    int win_start = local_end - MAX_ATTN_W;
    if (win_start < 0) win_start = 0;
    int L = local_end - win_start;

    int hh = blockIdx.y;
    int qbase = blockIdx.x * 128;
    int tid = threadIdx.x, warp = tid >> 5, lane = tid & 31;
    int g = lane >> 2, t = lane & 3;
    const float scale = 0.08838834764831845f;

    // Q fragments in registers, pre-scaled + rounded
    unsigned qa[16][4];
    {
        int r0 = qbase + warp * 16 + g, r1 = r0 + 8;
        const float* q0p = qbuf + (size_t)r0 * DIMC + hh * HD;
        const float* q1p = qbuf + (size_t)r1 * DIMC + hh * HD;
        bool v0 = r0 < S, v1 = r1 < S;
#pragma unroll
        for (int ks = 0; ks < 16; ks++) {
            int c = ks * 8 + t;
            qa[ks][0] = v0 ? f2tf(q0p[c] * scale) : 0u;
            qa[ks][1] = v1 ? f2tf(q1p[c] * scale) : 0u;
            qa[ks][2] = v0 ? f2tf(q0p[c + 4] * scale) : 0u;
            qa[ks][3] = v1 ? f2tf(q1p[c + 4] * scale) : 0u;
        }
    }

    float oacc[16][4];
#pragma unroll
    for (int nt = 0; nt < 16; nt++)
#pragma unroll
        for (int i = 0; i < 4; i++) oacc[nt][i] = 0.0f;
    float m0s = -1e30f, m1s = -1e30f, l0s = 0.0f, l1s = 0.0f;

    int prow0 = (warp * 16 + g) * 68, prow1 = prow0 + 8 * 68;
    int nkt = (L + 63) >> 6;

    const float* kwb = g_kw + (size_t)hh * PADW * HD;
    const float* vwb = g_vw + (size_t)hh * PADW * HD;

#define KVFILL(stg, kt)                                                       \
    {                                                                         \
        float* Ks_ = sm + (stg) * 17152;                                      \
        float* Vs_ = Ks_ + 8448;                                              \
        const float* kb_ = kwb + (size_t)(kt) * 64 * HD;                      \
        const float* vb_ = vwb + (size_t)(kt) * 64 * HD;                      \
        _Pragma("unroll")                                                     \
        for (int j = 0; j < 8; j++) {                                         \
            int idx = tid + j * 256;                                          \
            int row = idx >> 5, c4 = idx & 31;                                \
            cpa16(Ks_ + row * 132 + c4 * 4, kb_ + row * HD + c4 * 4);         \
            cpa16(Vs_ + row * 136 + c4 * 4, vb_ + row * HD + c4 * 4);         \
        }                                                                     \
    }

    KVFILL(0, 0); CP_COMMIT();
    for (int kt = 0; kt < nkt; kt++) {
        int s = kt & 1;
        if (kt + 1 < nkt) { KVFILL(s ^ 1, kt + 1); CP_COMMIT(); CP_WAIT(1); }
        else CP_WAIT(0);
        __syncthreads();
        const float* Ks = sm + s * 17152;
        const float* Vs = Ks + 8448;

        // S = Q K^T
        float sacc[8][4];
#pragma unroll
        for (int nt = 0; nt < 8; nt++)
#pragma unroll
            for (int i = 0; i < 4; i++) sacc[nt][i] = 0.0f;
#pragma unroll
        for (int ks = 0; ks < 16; ks++) {
            int d0 = ks * 8 + t;
#pragma unroll
            for (int nt = 0; nt < 8; nt++) {
                int key = nt * 8 + g;
                unsigned b0 = __float_as_uint(Ks[key * 132 + d0]);
                unsigned b1 = __float_as_uint(Ks[key * 132 + d0 + 4]);
                mma_tf32(sacc[nt], qa[ks], b0, b1);
            }
        }

        // mask + row max
        int colb = kt * 64 + 2 * t;
        float rmax0 = -1e30f, rmax1 = -1e30f;
#pragma unroll
        for (int nt = 0; nt < 8; nt++) {
            int c = colb + nt * 8;
            if (c >= L)     { sacc[nt][0] = -1e30f; sacc[nt][2] = -1e30f; }
            if (c + 1 >= L) { sacc[nt][1] = -1e30f; sacc[nt][3] = -1e30f; }
            rmax0 = fmaxf(rmax0, fmaxf(sacc[nt][0], sacc[nt][1]));
            rmax1 = fmaxf(rmax1, fmaxf(sacc[nt][2], sacc[nt][3]));
        }
        rmax0 = fmaxf(rmax0, __shfl_xor_sync(0xffffffffu, rmax0, 1));
        rmax0 = fmaxf(rmax0, __shfl_xor_sync(0xffffffffu, rmax0, 2));
        rmax1 = fmaxf(rmax1, __shfl_xor_sync(0xffffffffu, rmax1, 1));
        rmax1 = fmaxf(rmax1, __shfl_xor_sync(0xffffffffu, rmax1, 2));
        float newm0 = fmaxf(m0s, rmax0), newm1 = fmaxf(m1s, rmax1);
        float fac0 = __expf(m0s - newm0), fac1 = __expf(m1s - newm1);
        m0s = newm0; m1s = newm1;

        float rs0 = 0.0f, rs1 = 0.0f;
#pragma unroll
        for (int nt = 0; nt < 8; nt++) {
            float p0 = __expf(sacc[nt][0] - newm0);
            float p1 = __expf(sacc[nt][1] - newm0);
            float p2 = __expf(sacc[nt][2] - newm1);
            float p3 = __expf(sacc[nt][3] - newm1);
            rs0 += p0 + p1; rs1 += p2 + p3;
            int cn = nt * 8 + 2 * t;
            *(float2*)(Ps + prow0 + cn) = make_float2(f2tff(p0), f2tff(p1));
            *(float2*)(Ps + prow1 + cn) = make_float2(f2tff(p2), f2tff(p3));
        }
        rs0 += __shfl_xor_sync(0xffffffffu, rs0, 1);
        rs0 += __shfl_xor_sync(0xffffffffu, rs0, 2);
        rs1 += __shfl_xor_sync(0xffffffffu, rs1, 1);
        rs1 += __shfl_xor_sync(0xffffffffu, rs1, 2);
        l0s = l0s * fac0 + rs0;
        l1s = l1s * fac1 + rs1;
#pragma unroll
        for (int nt = 0; nt < 16; nt++) {
            oacc[nt][0] *= fac0; oacc[nt][1] *= fac0;
            oacc[nt][2] *= fac1; oacc[nt][3] *= fac1;
        }
        __syncwarp();  // P rows warp-private

        // O += P V
#pragma unroll
        for (int kk = 0; kk < 8; kk++) {
            int k0 = kk * 8 + t;
            unsigned pa[4];
            pa[0] = __float_as_uint(Ps[prow0 + k0]);
            pa[1] = __float_as_uint(Ps[prow1 + k0]);
            pa[2] = __float_as_uint(Ps[prow0 + k0 + 4]);
            pa[3] = __float_as_uint(Ps[prow1 + k0 + 4]);
            const float* v0r = Vs + k0 * 136 + g;
            const float* v1r = v0r + 4 * 136;
#pragma unroll
            for (int nt = 0; nt < 16; nt++) {
                unsigned b0 = __float_as_uint(v0r[nt * 8]);
                unsigned b1 = __float_as_uint(v1r[nt * 8]);
                mma_tf32(oacc[nt], pa, b0, b1);
            }
        }
        __syncthreads();
    }

    // epilogue (rounded, so out-GEMM needs no cvt)
    float inv0 = 1.0f / l0s, inv1 = 1.0f / l1s;
    int r0 = qbase + warp * 16 + g, r1 = r0 + 8;
#pragma unroll
    for (int nt = 0; nt < 16; nt++) {
        int d = hh * HD + nt * 8 + 2 * t;
        if (r0 < S)
            *(float2*)(obuf + (size_t)r0 * DIMC + d) =
                make_float2(f2tff(oacc[nt][0] * inv0), f2tff(oacc[nt][1] * inv0));
        if (r1 < S)
            *(float2*)(obuf + (size_t)r1 * DIMC + d) =
                make_float2(f2tff(oacc[nt][2] * inv1), f2tff(oacc[nt][3] * inv1));
    }
}

// ---------------------------------------------------------------------------
extern "C" void kernel_launch(void* const* d_in, const int* in_sizes, int n_in,
                              void* d_out, int out_size)
{
    const float* x   = (const float*)d_in[0];
    const float* th  = (const float*)d_in[1];
    const float* ck  = (const float*)d_in[2];
    const float* cv  = (const float*)d_in[3];
    const float* wq  = (const float*)d_in[4];
    const float* bq  = (const float*)d_in[5];
    const float* wk  = (const float*)d_in[6];
    const float* bk  = (const float*)d_in[7];
    const float* wv  = (const float*)d_in[8];
    const float* bv  = (const float*)d_in[9];
    const float* wo  = (const float*)d_in[10];
    const float* bo  = (const float*)d_in[11];
    const float* gq  = (const float*)d_in[12];
    const float* gk  = (const float*)d_in[13];
    const int* p_gh  = (const int*)d_in[15];
    const int* p_gw  = (const int*)d_in[16];
    const int* p_cs  = (const int*)d_in[17];
    const int* p_ge  = (const int*)d_in[18];
    const int* p_le  = (const int*)d_in[19];
    float* out = (float*)d_out;

    int S = in_sizes[0] / DIMC;

    float *qp, *kp, *vp, *op, *xrp, *wrp;
    cudaGetSymbolAddress((void**)&qp, g_q);
    cudaGetSymbolAddress((void**)&kp, g_k);
    cudaGetSymbolAddress((void**)&vp, g_v);
    cudaGetSymbolAddress((void**)&op, g_o);
    cudaGetSymbolAddress((void**)&xrp, g_xr);
    cudaGetSymbolAddress((void**)&wrp, g_wr);

    // --- prep: round weights + x ---
    int wn4 = DIMC * DIMC / 4;
    prep_round_kernel<<<(wn4 + 255) / 256, 256>>>(wq, wrp + 0 * DIMC * DIMC, wn4);
    prep_round_kernel<<<(wn4 + 255) / 256, 256>>>(wk, wrp + 1 * DIMC * DIMC, wn4);
    prep_round_kernel<<<(wn4 + 255) / 256, 256>>>(wv, wrp + 2 * DIMC * DIMC, wn4);
    prep_round_kernel<<<(wn4 + 255) / 256, 256>>>(wo, wrp + 3 * DIMC * DIMC, wn4);
    int xn4 = S * DIMC / 4;
    prep_round_kernel<<<(xn4 + 255) / 256, 256>>>(x, xrp, xn4);

    // --- QKV projections (fused z-grid) ---
    size_t gsm = 10240 * sizeof(float);  // 40KB
    cudaFuncSetAttribute(gemm_tc_kernel, cudaFuncAttributeMaxDynamicSharedMemorySize,
                         (int)gsm);
    dim3 gqkv((S + 127) / 128, DIMC / 128, 3);
    gemm_tc_kernel<<<gqkv, 256, gsm>>>(xrp, wrp, bq, bk, bv, qp, kp, vp, S, 3);

    // --- norm + rope ---
    norm_rope_kernel<<<dim3(S, 2), 256>>>(qp, kp, gq, gk, th, p_gh, p_gw, p_cs);

    // --- pack KV window ---
    int kvn = NHEADS * PADW * (HD / 4);
    prep_kv_kernel<<<(kvn + 255) / 256, 256>>>(kp, vp, ck, cv, S, p_cs, p_ge, p_le);

    // --- flash attention ---
    size_t fsm = (size_t)(34304 + 128 * 68) * sizeof(float);  // 172032 B
    cudaFuncSetAttribute(flash_tc_kernel, cudaFuncAttributeMaxDynamicSharedMemorySize,
                         (int)fsm);
    flash_tc_kernel<<<dim3((S + 127) / 128, NHEADS), 256, fsm>>>(
        qp, op, S, p_cs, p_ge, p_le);

    // --- output projection ---
    dim3 go((S + 127) / 128, DIMC / 128, 1);
    gemm_tc_kernel<<<go, 256, gsm>>>(op, wrp + (size_t)3 * DIMC * DIMC, bo, bo, bo,
                                     out, out, out, S, 1);
}

// round 8
// speedup vs baseline: 7.0537x; 1.7265x over previous
#include <cuda_runtime.h>
#include <cuda_fp16.h>
#include <math.h>

#define DIMC 1536
#define NHEADS 12
#define HD 128
#define MAX_ATTN_W 5632
#define MAXS 3200
#define PADW 5632

__device__ float  g_q[MAXS * DIMC];
__device__ float  g_k[MAXS * DIMC];
__device__ float  g_v[MAXS * DIMC];
__device__ __half g_xh[MAXS * DIMC];
__device__ __half g_oh[MAXS * DIMC];
__device__ __half g_wh[4 * DIMC * DIMC];
__device__ __half g_kw[NHEADS * PADW * HD];     // [h][key][d]
__device__ __half g_vwT[NHEADS * HD * PADW];    // [h][d][key]

__device__ __forceinline__ unsigned pk2(float a, float b) {
    __half2 h = __floats2half2_rn(a, b);
    return *(unsigned*)&h;
}

__device__ __forceinline__ void mma_f16(float* d, const unsigned* a,
                                        unsigned b0, unsigned b1) {
    asm volatile(
        "mma.sync.aligned.m16n8k16.row.col.f32.f16.f16.f32 "
        "{%0,%1,%2,%3}, {%4,%5,%6,%7}, {%8,%9}, {%0,%1,%2,%3};\n"
        : "+f"(d[0]), "+f"(d[1]), "+f"(d[2]), "+f"(d[3])
        : "r"(a[0]), "r"(a[1]), "r"(a[2]), "r"(a[3]), "r"(b0), "r"(b1));
}

__device__ __forceinline__ void cpa16(void* dst_smem, const void* src) {
    unsigned d = (unsigned)__cvta_generic_to_shared(dst_smem);
    asm volatile("cp.async.cg.shared.global [%0], [%1], 16;\n" :: "r"(d), "l"(src));
}
#define CP_COMMIT() asm volatile("cp.async.commit_group;\n" ::: "memory")

// ---------------------------------------------------------------------------
// prep: float -> half, 8 elems per thread
// ---------------------------------------------------------------------------
__global__ __launch_bounds__(256) void prep_half_kernel(
    const float* __restrict__ src, __half* __restrict__ dst, int n8)
{
    int i = blockIdx.x * 256 + threadIdx.x;
    if (i < n8) {
        float4 v0 = ((const float4*)src)[2 * i];
        float4 v1 = ((const float4*)src)[2 * i + 1];
        uint4 o;
        o.x = pk2(v0.x, v0.y); o.y = pk2(v0.z, v0.w);
        o.z = pk2(v1.x, v1.y); o.w = pk2(v1.z, v1.w);
        ((uint4*)dst)[i] = o;
    }
}

// ---------------------------------------------------------------------------
// prep KV: K -> [h][key][d] half; V -> [h][d][key] half (transposed). Zero pad.
// grid (88, NHEADS), 256 threads.
// ---------------------------------------------------------------------------
__global__ __launch_bounds__(256) void prep_kv_kernel(
    const float* __restrict__ kbuf, const float* __restrict__ vbuf,
    const float* __restrict__ cache_k, const float* __restrict__ cache_v, int S,
    const int* __restrict__ p_cs, const int* __restrict__ p_ge,
    const int* __restrict__ p_le)
{
    __shared__ __half vts[128][72];

    int cs = *p_cs, ge = *p_ge, le = *p_le;
    int local_end = le + cs + S - ge;
    int local_start = local_end - S;
    int win_start = local_end - MAX_ATTN_W;
    if (win_start < 0) win_start = 0;
    int L = local_end - win_start;

    int h = blockIdx.y;
    int j0 = blockIdx.x * 64;
    int tid = threadIdx.x;

#pragma unroll
    for (int i = 0; i < 8; i++) {
        int idx = tid + i * 256;
        int key = idx >> 5, c4 = idx & 31;
        int j = j0 + key;
        float4 kv = make_float4(0.f, 0.f, 0.f, 0.f), vv = kv;
        if (j < L) {
            int jg = win_start + j;
            const float *ks, *vs;
            if (jg < local_start) {
                size_t o = ((size_t)jg * NHEADS + h) * HD + c4 * 4;
                ks = cache_k + o; vs = cache_v + o;
            } else {
                size_t o = (size_t)(jg - local_start) * DIMC + h * HD + c4 * 4;
                ks = kbuf + o; vs = vbuf + o;
            }
            kv = *(const float4*)ks; vv = *(const float4*)vs;
        }
        uint2 ko; ko.x = pk2(kv.x, kv.y); ko.y = pk2(kv.z, kv.w);
        *(uint2*)(g_kw + ((size_t)h * PADW + j) * HD + c4 * 4) = ko;
        vts[c4 * 4 + 0][key] = __float2half_rn(vv.x);
        vts[c4 * 4 + 1][key] = __float2half_rn(vv.y);
        vts[c4 * 4 + 2][key] = __float2half_rn(vv.z);
        vts[c4 * 4 + 3][key] = __float2half_rn(vv.w);
    }
    __syncthreads();
#pragma unroll
    for (int i = 0; i < 4; i++) {
        int idx = tid + i * 256;
        int d = idx >> 3, c = idx & 7;
        *(uint4*)(g_vwT + ((size_t)h * HD + d) * PADW + j0 + c * 8) =
            *(uint4*)&vts[d][c * 8];
    }
}

// ---------------------------------------------------------------------------
// GEMM fp16: C[M,1536](f32) = A(h) @ W(h)^T + bias. BM=BN=128, BK=32,
// 256 thr, 8 warps (32x64 tiles), double-buffered cp.async.
// smem rows padded to 40 halves -> all frag loads conflict-free.
// ---------------------------------------------------------------------------
__global__ __launch_bounds__(256) void gemm_f16_kernel(
    const __half* __restrict__ A, const __half* __restrict__ Wbase,
    const float* __restrict__ b0p, const float* __restrict__ b1p,
    const float* __restrict__ b2p, float* __restrict__ C0,
    float* __restrict__ C1, float* __restrict__ C2, int M)
{
    extern __shared__ float smf[];
    __half* sh = (__half*)smf;
    int z = blockIdx.z;
    const __half* W = Wbase + (size_t)z * DIMC * DIMC;
    const float* bias = (z == 0) ? b0p : (z == 1) ? b1p : b2p;
    float* C = (z == 0) ? C0 : (z == 1) ? C1 : C2;

    int tid = threadIdx.x, warp = tid >> 5, lane = tid & 31;
    int g = lane >> 2, t = lane & 3;
    int wm = (warp & 3) * 32, wn = (warp >> 2) * 64;
    int bm = blockIdx.x * 128, bn = blockIdx.y * 128;

    float acc[2][8][4];
#pragma unroll
    for (int mt = 0; mt < 2; mt++)
#pragma unroll
        for (int nt = 0; nt < 8; nt++)
#pragma unroll
            for (int i = 0; i < 4; i++) acc[mt][nt][i] = 0.0f;

#define GF(stg, kt)                                                           \
    {                                                                         \
        __half* As_ = sh + (stg) * 10240;                                     \
        __half* Bs_ = As_ + 5120;                                             \
        const __half* Ag_ = A + (size_t)bm * DIMC + (kt) * 32;                \
        const __half* Wg_ = W + (size_t)bn * DIMC + (kt) * 32;                \
        _Pragma("unroll")                                                     \
        for (int j = 0; j < 2; j++) {                                         \
            int idx = tid + j * 256;                                          \
            int row = idx >> 2, c = idx & 3;                                  \
            cpa16(As_ + row * 40 + c * 8, Ag_ + (size_t)row * DIMC + c * 8);  \
            cpa16(Bs_ + row * 40 + c * 8, Wg_ + (size_t)row * DIMC + c * 8);  \
        }                                                                     \
    }

    GF(0, 0); CP_COMMIT();
    for (int kt = 0; kt < 48; kt++) {
        int s = kt & 1;
        if (kt + 1 < 48) {
            GF(s ^ 1, kt + 1); CP_COMMIT();
            asm volatile("cp.async.wait_group 1;\n" ::: "memory");
        } else {
            asm volatile("cp.async.wait_group 0;\n" ::: "memory");
        }
        __syncthreads();
        const __half* As = sh + s * 10240;
        const __half* Bs = As + 5120;
#pragma unroll
        for (int kst = 0; kst < 2; kst++) {
            int k0 = kst * 16 + 2 * t;
            unsigned af[2][4];
#pragma unroll
            for (int mt = 0; mt < 2; mt++) {
                int m0 = wm + mt * 16 + g;
                af[mt][0] = *(const unsigned*)(As + m0 * 40 + k0);
                af[mt][1] = *(const unsigned*)(As + (m0 + 8) * 40 + k0);
                af[mt][2] = *(const unsigned*)(As + m0 * 40 + k0 + 8);
                af[mt][3] = *(const unsigned*)(As + (m0 + 8) * 40 + k0 + 8);
            }
#pragma unroll
            for (int nt = 0; nt < 8; nt++) {
                int n = wn + nt * 8 + g;
                unsigned bf0 = *(const unsigned*)(Bs + n * 40 + k0);
                unsigned bf1 = *(const unsigned*)(Bs + n * 40 + k0 + 8);
                mma_f16(acc[0][nt], af[0], bf0, bf1);
                mma_f16(acc[1][nt], af[1], bf0, bf1);
            }
        }
        __syncthreads();
    }
#pragma unroll
    for (int mt = 0; mt < 2; mt++) {
        int m0 = bm + wm + mt * 16 + g, m1 = m0 + 8;
#pragma unroll
        for (int nt = 0; nt < 8; nt++) {
            int n = bn + wn + nt * 8 + 2 * t;
            float bb0 = bias[n], bb1 = bias[n + 1];
            if (m0 < M)
                *(float2*)(C + (size_t)m0 * DIMC + n) =
                    make_float2(acc[mt][nt][0] + bb0, acc[mt][nt][1] + bb1);
            if (m1 < M)
                *(float2*)(C + (size_t)m1 * DIMC + n) =
                    make_float2(acc[mt][nt][2] + bb0, acc[mt][nt][3] + bb1);
        }
    }
}

// ---------------------------------------------------------------------------
// RMSNorm + 3-axis causal RoPE (fp32, unchanged)
// ---------------------------------------------------------------------------
__global__ __launch_bounds__(256) void norm_rope_kernel(
    float* __restrict__ qb, float* __restrict__ kb,
    const float* __restrict__ gq, const float* __restrict__ gk,
    const float* __restrict__ theta,
    const int* __restrict__ p_gh, const int* __restrict__ p_gw,
    const int* __restrict__ p_cs)
{
    __shared__ float row[DIMC];
    __shared__ float red[256];

    int srow = blockIdx.x;
    int which = blockIdx.y;
    float* buf = which ? kb : qb;
    const float* g = which ? gk : gq;
    float* rptr = buf + (size_t)srow * DIMC;

    int tid = threadIdx.x;
    float vals[6];
    float ss = 0.0f;
#pragma unroll
    for (int q = 0; q < 6; q++) {
        int d = tid + q * 256;
        float v = rptr[d];
        vals[q] = v;
        ss += v * v;
    }
    red[tid] = ss;
    __syncthreads();
    for (int o = 128; o > 0; o >>= 1) {
        if (tid < o) red[tid] += red[tid + o];
        __syncthreads();
    }
    float scale = rsqrtf(red[0] * (1.0f / DIMC) + 1e-6f);
#pragma unroll
    for (int q = 0; q < 6; q++) {
        int d = tid + q * 256;
        row[d] = vals[q] * scale * g[d];
    }
    __syncthreads();

    int gh = *p_gh, gw = *p_gw, cs = *p_cs;
    int fs = gh * gw;
    int sf = cs / fs;
    int f = srow / fs;
    int rem = srow - f * fs;
    int h = rem / gw;
    int w = rem - h * gw;

    for (int p = tid; p < NHEADS * (HD / 2); p += 256) {
        int head = p >> 6;
        int i = p & 63;
        int trow = (i < 22) ? (sf + f) : ((i < 43) ? h : w);
        float ang = theta[trow * (HD / 2) + i];
        float sn, cn;
        __sincosf(ang, &sn, &cn);
        int d0 = head * HD + 2 * i;
        float xr = row[d0], xi = row[d0 + 1];
        rptr[d0]     = xr * cn - xi * sn;
        rptr[d0 + 1] = xr * sn + xi * cn;
    }
}

// ---------------------------------------------------------------------------
// Flash attention, fp16 mma. BM=128 (8 warps x 16 rows), BN=64.
// K [key][136h], V^T [d][72h], P [row][72h]; all frag loads conflict-free.
// Double-buffered cp.async from packed half windows.
// ---------------------------------------------------------------------------
__global__ __launch_bounds__(256) void flash_f16_kernel(
    const float* __restrict__ qbuf, __half* __restrict__ obuf, int S,
    const int* __restrict__ p_cs, const int* __restrict__ p_ge,
    const int* __restrict__ p_le)
{
    extern __shared__ float smf[];
    __half* sh = (__half*)smf;
    __half* Ps = sh + 35840;     // 128*72 halves

    int cs = *p_cs, ge = *p_ge, le = *p_le;
    int local_end = le + cs + S - ge;
    int win_start = local_end - MAX_ATTN_W;
    if (win_start < 0) win_start = 0;
    int L = local_end - win_start;

    int hh = blockIdx.y;
    int qbase = blockIdx.x * 128;
    int tid = threadIdx.x, warp = tid >> 5, lane = tid & 31;
    int g = lane >> 2, t = lane & 3;
    const float scale = 0.08838834764831845f;

    // Q fragments (8 k-steps of 16), pre-scaled, packed half2
    unsigned qa[8][4];
    {
        int r0 = qbase + warp * 16 + g, r1 = r0 + 8;
        const float* q0p = qbuf + (size_t)r0 * DIMC + hh * HD;
        const float* q1p = qbuf + (size_t)r1 * DIMC + hh * HD;
        bool v0 = r0 < S, v1 = r1 < S;
#pragma unroll
        for (int ks = 0; ks < 8; ks++) {
            int c = ks * 16 + 2 * t;
            qa[ks][0] = v0 ? pk2(q0p[c] * scale, q0p[c + 1] * scale) : 0u;
            qa[ks][1] = v1 ? pk2(q1p[c] * scale, q1p[c + 1] * scale) : 0u;
            qa[ks][2] = v0 ? pk2(q0p[c + 8] * scale, q0p[c + 9] * scale) : 0u;
            qa[ks][3] = v1 ? pk2(q1p[c + 8] * scale, q1p[c + 9] * scale) : 0u;
        }
    }

    float oacc[16][4];
#pragma unroll
    for (int nt = 0; nt < 16; nt++)
#pragma unroll
        for (int i = 0; i < 4; i++) oacc[nt][i] = 0.0f;
    float m0s = -1e30f, m1s = -1e30f, l0s = 0.0f, l1s = 0.0f;

    int prow0 = (warp * 16 + g) * 72, prow1 = prow0 + 8 * 72;
    int nkt = (L + 63) >> 6;

    const __half* kwb = g_kw + (size_t)hh * PADW * HD;
    const __half* vwb = g_vwT + (size_t)hh * HD * PADW;

#define KVF(stg, kt)                                                          \
    {                                                                         \
        __half* Ks_ = sh + (stg) * 17920;                                     \
        __half* Vt_ = Ks_ + 8704;                                             \
        const __half* kb_ = kwb + (size_t)(kt) * 64 * HD;                     \
        _Pragma("unroll")                                                     \
        for (int j = 0; j < 4; j++) {                                         \
            int idx = tid + j * 256;                                          \
            int row = idx >> 4, c = idx & 15;                                 \
            cpa16(Ks_ + row * 136 + c * 8, kb_ + (size_t)row * HD + c * 8);   \
        }                                                                     \
        _Pragma("unroll")                                                     \
        for (int j = 0; j < 4; j++) {                                         \
            int idx = tid + j * 256;                                          \
            int row = idx >> 3, c = idx & 7;                                  \
            cpa16(Vt_ + row * 72 + c * 8,                                     \
                  vwb + (size_t)row * PADW + (kt) * 64 + c * 8);              \
        }                                                                     \
    }

    KVF(0, 0); CP_COMMIT();
    for (int kt = 0; kt < nkt; kt++) {
        int s = kt & 1;
        if (kt + 1 < nkt) {
            KVF(s ^ 1, kt + 1); CP_COMMIT();
            asm volatile("cp.async.wait_group 1;\n" ::: "memory");
        } else {
            asm volatile("cp.async.wait_group 0;\n" ::: "memory");
        }
        __syncthreads();
        const __half* Ks = sh + s * 17920;
        const __half* Vt = Ks + 8704;

        // S = Q K^T
        float sacc[8][4];
#pragma unroll
        for (int nt = 0; nt < 8; nt++)
#pragma unroll
            for (int i = 0; i < 4; i++) sacc[nt][i] = 0.0f;
#pragma unroll
        for (int ks = 0; ks < 8; ks++) {
            int k0 = ks * 16 + 2 * t;
#pragma unroll
            for (int nt = 0; nt < 8; nt++) {
                int key = nt * 8 + g;
                unsigned b0 = *(const unsigned*)(Ks + key * 136 + k0);
                unsigned b1 = *(const unsigned*)(Ks + key * 136 + k0 + 8);
                mma_f16(sacc[nt], qa[ks], b0, b1);
            }
        }

        // mask + row max
        int colb = kt * 64 + 2 * t;
        float rmax0 = -1e30f, rmax1 = -1e30f;
#pragma unroll
        for (int nt = 0; nt < 8; nt++) {
            int c = colb + nt * 8;
            if (c >= L)     { sacc[nt][0] = -1e30f; sacc[nt][2] = -1e30f; }
            if (c + 1 >= L) { sacc[nt][1] = -1e30f; sacc[nt][3] = -1e30f; }
            rmax0 = fmaxf(rmax0, fmaxf(sacc[nt][0], sacc[nt][1]));
            rmax1 = fmaxf(rmax1, fmaxf(sacc[nt][2], sacc[nt][3]));
        }
        rmax0 = fmaxf(rmax0, __shfl_xor_sync(0xffffffffu, rmax0, 1));
        rmax0 = fmaxf(rmax0, __shfl_xor_sync(0xffffffffu, rmax0, 2));
        rmax1 = fmaxf(rmax1, __shfl_xor_sync(0xffffffffu, rmax1, 1));
        rmax1 = fmaxf(rmax1, __shfl_xor_sync(0xffffffffu, rmax1, 2));
        float newm0 = fmaxf(m0s, rmax0), newm1 = fmaxf(m1s, rmax1);
        float fac0 = __expf(m0s - newm0), fac1 = __expf(m1s - newm1);
        m0s = newm0; m1s = newm1;

        float rs0 = 0.0f, rs1 = 0.0f;
#pragma unroll
        for (int nt = 0; nt < 8; nt++) {
            float p0 = __expf(sacc[nt][0] - newm0);
            float p1 = __expf(sacc[nt][1] - newm0);
            float p2 = __expf(sacc[nt][2] - newm1);
            float p3 = __expf(sacc[nt][3] - newm1);
            rs0 += p0 + p1; rs1 += p2 + p3;
            int cn = nt * 8 + 2 * t;
            *(unsigned*)(Ps + prow0 + cn) = pk2(p0, p1);
            *(unsigned*)(Ps + prow1 + cn) = pk2(p2, p3);
        }
        rs0 += __shfl_xor_sync(0xffffffffu, rs0, 1);
        rs0 += __shfl_xor_sync(0xffffffffu, rs0, 2);
        rs1 += __shfl_xor_sync(0xffffffffu, rs1, 1);
        rs1 += __shfl_xor_sync(0xffffffffu, rs1, 2);
        l0s = l0s * fac0 + rs0;
        l1s = l1s * fac1 + rs1;
#pragma unroll
        for (int nt = 0; nt < 16; nt++) {
            oacc[nt][0] *= fac0; oacc[nt][1] *= fac0;
            oacc[nt][2] *= fac1; oacc[nt][3] *= fac1;
        }
        __syncwarp();  // P rows warp-private

        // O += P V  (A = P over 4 k-steps of 16 keys; B = V^T)
#pragma unroll
        for (int kk = 0; kk < 4; kk++) {
            int k0 = kk * 16 + 2 * t;
            unsigned pa[4];
            pa[0] = *(const unsigned*)(Ps + prow0 + k0);
            pa[1] = *(const unsigned*)(Ps + prow1 + k0);
            pa[2] = *(const unsigned*)(Ps + prow0 + k0 + 8);
            pa[3] = *(const unsigned*)(Ps + prow1 + k0 + 8);
#pragma unroll
            for (int nt = 0; nt < 16; nt++) {
                int d = nt * 8 + g;
                unsigned b0 = *(const unsigned*)(Vt + d * 72 + k0);
                unsigned b1 = *(const unsigned*)(Vt + d * 72 + k0 + 8);
                mma_f16(oacc[nt], pa, b0, b1);
            }
        }
        __syncthreads();
    }

    // epilogue: write half O for the output projection
    float inv0 = 1.0f / l0s, inv1 = 1.0f / l1s;
    int r0 = qbase + warp * 16 + g, r1 = r0 + 8;
#pragma unroll
    for (int nt = 0; nt < 16; nt++) {
        int d = hh * HD + nt * 8 + 2 * t;
        if (r0 < S)
            *(unsigned*)(obuf + (size_t)r0 * DIMC + d) =
                pk2(oacc[nt][0] * inv0, oacc[nt][1] * inv0);
        if (r1 < S)
            *(unsigned*)(obuf + (size_t)r1 * DIMC + d) =
                pk2(oacc[nt][2] * inv1, oacc[nt][3] * inv1);
    }
}

// ---------------------------------------------------------------------------
extern "C" void kernel_launch(void* const* d_in, const int* in_sizes, int n_in,
                              void* d_out, int out_size)
{
    const float* x   = (const float*)d_in[0];
    const float* th  = (const float*)d_in[1];
    const float* ck  = (const float*)d_in[2];
    const float* cv  = (const float*)d_in[3];
    const float* wq  = (const float*)d_in[4];
    const float* bq  = (const float*)d_in[5];
    const float* wk  = (const float*)d_in[6];
    const float* bk  = (const float*)d_in[7];
    const float* wv  = (const float*)d_in[8];
    const float* bv  = (const float*)d_in[9];
    const float* wo  = (const float*)d_in[10];
    const float* bo  = (const float*)d_in[11];
    const float* gq  = (const float*)d_in[12];
    const float* gk  = (const float*)d_in[13];
    const int* p_gh  = (const int*)d_in[15];
    const int* p_gw  = (const int*)d_in[16];
    const int* p_cs  = (const int*)d_in[17];
    const int* p_ge  = (const int*)d_in[18];
    const int* p_le  = (const int*)d_in[19];
    float* out = (float*)d_out;

    int S = in_sizes[0] / DIMC;

    float *qp, *kp, *vp;
    __half *xhp, *ohp, *whp;
    cudaGetSymbolAddress((void**)&qp, g_q);
    cudaGetSymbolAddress((void**)&kp, g_k);
    cudaGetSymbolAddress((void**)&vp, g_v);
    cudaGetSymbolAddress((void**)&xhp, g_xh);
    cudaGetSymbolAddress((void**)&ohp, g_oh);
    cudaGetSymbolAddress((void**)&whp, g_wh);

    int wn8 = DIMC * DIMC / 8;
    prep_half_kernel<<<(wn8 + 255) / 256, 256>>>(wq, whp + 0 * DIMC * DIMC, wn8);
    prep_half_kernel<<<(wn8 + 255) / 256, 256>>>(wk, whp + 1 * DIMC * DIMC, wn8);
    prep_half_kernel<<<(wn8 + 255) / 256, 256>>>(wv, whp + 2 * DIMC * DIMC, wn8);
    prep_half_kernel<<<(wn8 + 255) / 256, 256>>>(wo, whp + 3 * DIMC * DIMC, wn8);
    int xn8 = S * DIMC / 8;
    prep_half_kernel<<<(xn8 + 255) / 256, 256>>>(x, xhp, xn8);

    size_t gsm = 40960;  // 2 stages * (As+Bs) halves
    cudaFuncSetAttribute(gemm_f16_kernel, cudaFuncAttributeMaxDynamicSharedMemorySize,
                         (int)gsm);
    dim3 gqkv((S + 127) / 128, DIMC / 128, 3);
    gemm_f16_kernel<<<gqkv, 256, gsm>>>(xhp, whp, bq, bk, bv, qp, kp, vp, S);

    norm_rope_kernel<<<dim3(S, 2), 256>>>(qp, kp, gq, gk, th, p_gh, p_gw, p_cs);

    prep_kv_kernel<<<dim3(PADW / 64, NHEADS), 256>>>(kp, vp, ck, cv, S,
                                                     p_cs, p_ge, p_le);

    size_t fsm = (size_t)(35840 + 128 * 72) * sizeof(__half);  // 90112 B
    cudaFuncSetAttribute(flash_f16_kernel, cudaFuncAttributeMaxDynamicSharedMemorySize,
                         (int)fsm);
    flash_f16_kernel<<<dim3((S + 127) / 128, NHEADS), 256, fsm>>>(
        qp, ohp, S, p_cs, p_ge, p_le);

    dim3 go((S + 127) / 128, DIMC / 128, 1);
    gemm_f16_kernel<<<go, 256, gsm>>>(ohp, whp + (size_t)3 * DIMC * DIMC,
                                      bo, bo, bo, out, out, out, S);
}

// round 9
// speedup vs baseline: 7.0823x; 1.0040x over previous
#include <cuda_runtime.h>
#include <cuda_fp16.h>
#include <math.h>

#define DIMC 1536
#define NHEADS 12
#define HD 128
#define MAX_ATTN_W 5632
#define MAXS 3200
#define PADW 5632

__device__ float  g_q[MAXS * DIMC];
__device__ float  g_k[MAXS * DIMC];
__device__ float  g_v[MAXS * DIMC];
__device__ __half g_xh[MAXS * DIMC];
__device__ __half g_oh[MAXS * DIMC];
__device__ __half g_wh[4 * DIMC * DIMC];
__device__ __half g_kw[NHEADS * PADW * HD];     // [h][key][d]
__device__ __half g_vwT[NHEADS * HD * PADW];    // [h][d][key]

__device__ __forceinline__ unsigned pk2(float a, float b) {
    __half2 h = __floats2half2_rn(a, b);
    return *(unsigned*)&h;
}

__device__ __forceinline__ void mma_f16(float* d, const unsigned* a,
                                        unsigned b0, unsigned b1) {
    asm volatile(
        "mma.sync.aligned.m16n8k16.row.col.f32.f16.f16.f32 "
        "{%0,%1,%2,%3}, {%4,%5,%6,%7}, {%8,%9}, {%0,%1,%2,%3};\n"
        : "+f"(d[0]), "+f"(d[1]), "+f"(d[2]), "+f"(d[3])
        : "r"(a[0]), "r"(a[1]), "r"(a[2]), "r"(a[3]), "r"(b0), "r"(b1));
}

__device__ __forceinline__ void cpa16(void* dst_smem, const void* src) {
    unsigned d = (unsigned)__cvta_generic_to_shared(dst_smem);
    asm volatile("cp.async.cg.shared.global [%0], [%1], 16;\n" :: "r"(d), "l"(src));
}
#define CP_COMMIT() asm volatile("cp.async.commit_group;\n" ::: "memory")

// ---------------------------------------------------------------------------
// prep: float -> half, 8 elems per thread (single launch for all weights)
// ---------------------------------------------------------------------------
__global__ __launch_bounds__(256) void prep_half_kernel(
    const float* __restrict__ s0, const float* __restrict__ s1,
    const float* __restrict__ s2, const float* __restrict__ s3,
    __half* __restrict__ dst, int n8_each)
{
    int i = blockIdx.x * 256 + threadIdx.x;
    int total = (s1 ? 4 : 1) * n8_each;
    if (i >= total) return;
    int wsel = i / n8_each, r = i - wsel * n8_each;
    const float* src = (wsel == 0) ? s0 : (wsel == 1) ? s1 : (wsel == 2) ? s2 : s3;
    float4 v0 = ((const float4*)src)[2 * r];
    float4 v1 = ((const float4*)src)[2 * r + 1];
    uint4 o;
    o.x = pk2(v0.x, v0.y); o.y = pk2(v0.z, v0.w);
    o.z = pk2(v1.x, v1.y); o.w = pk2(v1.z, v1.w);
    ((uint4*)dst)[i] = o;
}

// ---------------------------------------------------------------------------
// prep KV: K -> [h][key][d] half; V -> [h][d][key] half (transposed). Zero pad.
// grid (88, NHEADS), 256 threads.
// ---------------------------------------------------------------------------
__global__ __launch_bounds__(256) void prep_kv_kernel(
    const float* __restrict__ kbuf, const float* __restrict__ vbuf,
    const float* __restrict__ cache_k, const float* __restrict__ cache_v, int S,
    const int* __restrict__ p_cs, const int* __restrict__ p_ge,
    const int* __restrict__ p_le)
{
    __shared__ __half vts[128][72];

    int cs = *p_cs, ge = *p_ge, le = *p_le;
    int local_end = le + cs + S - ge;
    int local_start = local_end - S;
    int win_start = local_end - MAX_ATTN_W;
    if (win_start < 0) win_start = 0;
    int L = local_end - win_start;

    int h = blockIdx.y;
    int j0 = blockIdx.x * 64;
    int tid = threadIdx.x;

#pragma unroll
    for (int i = 0; i < 8; i++) {
        int idx = tid + i * 256;
        int key = idx >> 5, c4 = idx & 31;
        int j = j0 + key;
        float4 kv = make_float4(0.f, 0.f, 0.f, 0.f), vv = kv;
        if (j < L) {
            int jg = win_start + j;
            const float *ks, *vs;
            if (jg < local_start) {
                size_t o = ((size_t)jg * NHEADS + h) * HD + c4 * 4;
                ks = cache_k + o; vs = cache_v + o;
            } else {
                size_t o = (size_t)(jg - local_start) * DIMC + h * HD + c4 * 4;
                ks = kbuf + o; vs = vbuf + o;
            }
            kv = *(const float4*)ks; vv = *(const float4*)vs;
        }
        uint2 ko; ko.x = pk2(kv.x, kv.y); ko.y = pk2(kv.z, kv.w);
        *(uint2*)(g_kw + ((size_t)h * PADW + j) * HD + c4 * 4) = ko;
        vts[c4 * 4 + 0][key] = __float2half_rn(vv.x);
        vts[c4 * 4 + 1][key] = __float2half_rn(vv.y);
        vts[c4 * 4 + 2][key] = __float2half_rn(vv.z);
        vts[c4 * 4 + 3][key] = __float2half_rn(vv.w);
    }
    __syncthreads();
#pragma unroll
    for (int i = 0; i < 4; i++) {
        int idx = tid + i * 256;
        int d = idx >> 3, c = idx & 7;
        *(uint4*)(g_vwT + ((size_t)h * HD + d) * PADW + j0 + c * 8) =
            *(uint4*)&vts[d][c * 8];
    }
}

// ---------------------------------------------------------------------------
// GEMM fp16: C[M,1536](f32) = A(h) @ W(h)^T + bias. BM=64, BN=128, BK=32.
// 128 threads (4 warps x 16 rows, full-N per warp), double-buffered cp.async.
// smem rows 40 halves (conflict-free frag loads).
// ---------------------------------------------------------------------------
__global__ __launch_bounds__(128) void gemm_f16_kernel(
    const __half* __restrict__ A, const __half* __restrict__ Wbase,
    const float* __restrict__ b0p, const float* __restrict__ b1p,
    const float* __restrict__ b2p, float* __restrict__ C0,
    float* __restrict__ C1, float* __restrict__ C2, int M)
{
    extern __shared__ float smf[];
    __half* sh = (__half*)smf;
    int z = blockIdx.z;
    const __half* W = Wbase + (size_t)z * DIMC * DIMC;
    const float* bias = (z == 0) ? b0p : (z == 1) ? b1p : b2p;
    float* C = (z == 0) ? C0 : (z == 1) ? C1 : C2;

    int tid = threadIdx.x, warp = tid >> 5, lane = tid & 31;
    int g = lane >> 2, t = lane & 3;
    int wm = warp * 16;
    int bm = blockIdx.x * 64, bn = blockIdx.y * 128;

    float acc[16][4];
#pragma unroll
    for (int nt = 0; nt < 16; nt++)
#pragma unroll
        for (int i = 0; i < 4; i++) acc[nt][i] = 0.0f;

    // stage: A 64*40 halves, B 128*40 halves -> 7680 halves per stage
#define GF(stg, kt)                                                           \
    {                                                                         \
        __half* As_ = sh + (stg) * 7680;                                      \
        __half* Bs_ = As_ + 2560;                                             \
        const __half* Ag_ = A + (size_t)bm * DIMC + (kt) * 32;                \
        const __half* Wg_ = W + (size_t)bn * DIMC + (kt) * 32;                \
        _Pragma("unroll")                                                     \
        for (int j = 0; j < 2; j++) {                                         \
            int idx = tid + j * 128;                                          \
            int row = idx >> 2, c = idx & 3;                                  \
            cpa16(As_ + row * 40 + c * 8, Ag_ + (size_t)row * DIMC + c * 8);  \
        }                                                                     \
        _Pragma("unroll")                                                     \
        for (int j = 0; j < 4; j++) {                                         \
            int idx = tid + j * 128;                                          \
            int row = idx >> 2, c = idx & 3;                                  \
            cpa16(Bs_ + row * 40 + c * 8, Wg_ + (size_t)row * DIMC + c * 8);  \
        }                                                                     \
    }

    GF(0, 0); CP_COMMIT();
    for (int kt = 0; kt < 48; kt++) {
        int s = kt & 1;
        if (kt + 1 < 48) {
            GF(s ^ 1, kt + 1); CP_COMMIT();
            asm volatile("cp.async.wait_group 1;\n" ::: "memory");
        } else {
            asm volatile("cp.async.wait_group 0;\n" ::: "memory");
        }
        __syncthreads();
        const __half* As = sh + s * 7680;
        const __half* Bs = As + 2560;
#pragma unroll
        for (int kst = 0; kst < 2; kst++) {
            int k0 = kst * 16 + 2 * t;
            unsigned af[4];
            int m0 = wm + g;
            af[0] = *(const unsigned*)(As + m0 * 40 + k0);
            af[1] = *(const unsigned*)(As + (m0 + 8) * 40 + k0);
            af[2] = *(const unsigned*)(As + m0 * 40 + k0 + 8);
            af[3] = *(const unsigned*)(As + (m0 + 8) * 40 + k0 + 8);
#pragma unroll
            for (int nt = 0; nt < 16; nt++) {
                int n = nt * 8 + g;
                unsigned bf0 = *(const unsigned*)(Bs + n * 40 + k0);
                unsigned bf1 = *(const unsigned*)(Bs + n * 40 + k0 + 8);
                mma_f16(acc[nt], af, bf0, bf1);
            }
        }
        __syncthreads();
    }
    int m0 = bm + wm + g, m1 = m0 + 8;
#pragma unroll
    for (int nt = 0; nt < 16; nt++) {
        int n = bn + nt * 8 + 2 * t;
        float bb0 = bias[n], bb1 = bias[n + 1];
        if (m0 < M)
            *(float2*)(C + (size_t)m0 * DIMC + n) =
                make_float2(acc[nt][0] + bb0, acc[nt][1] + bb1);
        if (m1 < M)
            *(float2*)(C + (size_t)m1 * DIMC + n) =
                make_float2(acc[nt][2] + bb0, acc[nt][3] + bb1);
    }
}

// ---------------------------------------------------------------------------
// RMSNorm + 3-axis causal RoPE (fp32, unchanged)
// ---------------------------------------------------------------------------
__global__ __launch_bounds__(256) void norm_rope_kernel(
    float* __restrict__ qb, float* __restrict__ kb,
    const float* __restrict__ gq, const float* __restrict__ gk,
    const float* __restrict__ theta,
    const int* __restrict__ p_gh, const int* __restrict__ p_gw,
    const int* __restrict__ p_cs)
{
    __shared__ float row[DIMC];
    __shared__ float red[256];

    int srow = blockIdx.x;
    int which = blockIdx.y;
    float* buf = which ? kb : qb;
    const float* g = which ? gk : gq;
    float* rptr = buf + (size_t)srow * DIMC;

    int tid = threadIdx.x;
    float vals[6];
    float ss = 0.0f;
#pragma unroll
    for (int q = 0; q < 6; q++) {
        int d = tid + q * 256;
        float v = rptr[d];
        vals[q] = v;
        ss += v * v;
    }
    red[tid] = ss;
    __syncthreads();
    for (int o = 128; o > 0; o >>= 1) {
        if (tid < o) red[tid] += red[tid + o];
        __syncthreads();
    }
    float scale = rsqrtf(red[0] * (1.0f / DIMC) + 1e-6f);
#pragma unroll
    for (int q = 0; q < 6; q++) {
        int d = tid + q * 256;
        row[d] = vals[q] * scale * g[d];
    }
    __syncthreads();

    int gh = *p_gh, gw = *p_gw, cs = *p_cs;
    int fs = gh * gw;
    int sf = cs / fs;
    int f = srow / fs;
    int rem = srow - f * fs;
    int h = rem / gw;
    int w = rem - h * gw;

    for (int p = tid; p < NHEADS * (HD / 2); p += 256) {
        int head = p >> 6;
        int i = p & 63;
        int trow = (i < 22) ? (sf + f) : ((i < 43) ? h : w);
        float ang = theta[trow * (HD / 2) + i];
        float sn, cn;
        __sincosf(ang, &sn, &cn);
        int d0 = head * HD + 2 * i;
        float xr = row[d0], xi = row[d0 + 1];
        rptr[d0]     = xr * cn - xi * sn;
        rptr[d0 + 1] = xr * sn + xi * cn;
    }
}

// ---------------------------------------------------------------------------
// Flash attention, fp16 mma. BM=64 (4 warps x 16 rows), BN=64 keys.
// grid (49, 12) = 588 CTAs -> clean 2-round packing at 2 CTAs/SM.
// K [key][136h], V^T [d][72h], P [row][72h]; conflict-free frag loads.
// ---------------------------------------------------------------------------
__global__ __launch_bounds__(128) void flash_f16_kernel(
    const float* __restrict__ qbuf, __half* __restrict__ obuf, int S,
    const int* __restrict__ p_cs, const int* __restrict__ p_ge,
    const int* __restrict__ p_le)
{
    extern __shared__ float smf[];
    __half* sh = (__half*)smf;
    __half* Ps = sh + 35840;     // 64*72 halves

    int cs = *p_cs, ge = *p_ge, le = *p_le;
    int local_end = le + cs + S - ge;
    int win_start = local_end - MAX_ATTN_W;
    if (win_start < 0) win_start = 0;
    int L = local_end - win_start;

    int hh = blockIdx.y;
    int qbase = blockIdx.x * 64;
    int tid = threadIdx.x, warp = tid >> 5, lane = tid & 31;
    int g = lane >> 2, t = lane & 3;
    const float scale = 0.08838834764831845f;

    unsigned qa[8][4];
    {
        int r0 = qbase + warp * 16 + g, r1 = r0 + 8;
        const float* q0p = qbuf + (size_t)r0 * DIMC + hh * HD;
        const float* q1p = qbuf + (size_t)r1 * DIMC + hh * HD;
        bool v0 = r0 < S, v1 = r1 < S;
#pragma unroll
        for (int ks = 0; ks < 8; ks++) {
            int c = ks * 16 + 2 * t;
            qa[ks][0] = v0 ? pk2(q0p[c] * scale, q0p[c + 1] * scale) : 0u;
            qa[ks][1] = v1 ? pk2(q1p[c] * scale, q1p[c + 1] * scale) : 0u;
            qa[ks][2] = v0 ? pk2(q0p[c + 8] * scale, q0p[c + 9] * scale) : 0u;
            qa[ks][3] = v1 ? pk2(q1p[c + 8] * scale, q1p[c + 9] * scale) : 0u;
        }
    }

    float oacc[16][4];
#pragma unroll
    for (int nt = 0; nt < 16; nt++)
#pragma unroll
        for (int i = 0; i < 4; i++) oacc[nt][i] = 0.0f;
    float m0s = -1e30f, m1s = -1e30f, l0s = 0.0f, l1s = 0.0f;

    int prow0 = (warp * 16 + g) * 72, prow1 = prow0 + 8 * 72;
    int nkt = (L + 63) >> 6;

    const __half* kwb = g_kw + (size_t)hh * PADW * HD;
    const __half* vwb = g_vwT + (size_t)hh * HD * PADW;

#define KVF(stg, kt)                                                          \
    {                                                                         \
        __half* Ks_ = sh + (stg) * 17920;                                     \
        __half* Vt_ = Ks_ + 8704;                                             \
        const __half* kb_ = kwb + (size_t)(kt) * 64 * HD;                     \
        _Pragma("unroll")                                                     \
        for (int j = 0; j < 8; j++) {                                         \
            int idx = tid + j * 128;                                          \
            int row = idx >> 4, c = idx & 15;                                 \
            cpa16(Ks_ + row * 136 + c * 8, kb_ + (size_t)row * HD + c * 8);   \
        }                                                                     \
        _Pragma("unroll")                                                     \
        for (int j = 0; j < 8; j++) {                                         \
            int idx = tid + j * 128;                                          \
            int row = idx >> 3, c = idx & 7;                                  \
            cpa16(Vt_ + row * 72 + c * 8,                                     \
                  vwb + (size_t)row * PADW + (kt) * 64 + c * 8);              \
        }                                                                     \
    }

    KVF(0, 0); CP_COMMIT();
    for (int kt = 0; kt < nkt; kt++) {
        int s = kt & 1;
        if (kt + 1 < nkt) {
            KVF(s ^ 1, kt + 1); CP_COMMIT();
            asm volatile("cp.async.wait_group 1;\n" ::: "memory");
        } else {
            asm volatile("cp.async.wait_group 0;\n" ::: "memory");
        }
        __syncthreads();
        const __half* Ks = sh + s * 17920;
        const __half* Vt = Ks + 8704;

        float sacc[8][4];
#pragma unroll
        for (int nt = 0; nt < 8; nt++)
#pragma unroll
            for (int i = 0; i < 4; i++) sacc[nt][i] = 0.0f;
#pragma unroll
        for (int ks = 0; ks < 8; ks++) {
            int k0 = ks * 16 + 2 * t;
#pragma unroll
            for (int nt = 0; nt < 8; nt++) {
                int key = nt * 8 + g;
                unsigned b0 = *(const unsigned*)(Ks + key * 136 + k0);
                unsigned b1 = *(const unsigned*)(Ks + key * 136 + k0 + 8);
                mma_f16(sacc[nt], qa[ks], b0, b1);
            }
        }

        int colb = kt * 64 + 2 * t;
        float rmax0 = -1e30f, rmax1 = -1e30f;
#pragma unroll
        for (int nt = 0; nt < 8; nt++) {
            int c = colb + nt * 8;
            if (c >= L)     { sacc[nt][0] = -1e30f; sacc[nt][2] = -1e30f; }
            if (c + 1 >= L) { sacc[nt][1] = -1e30f; sacc[nt][3] = -1e30f; }
            rmax0 = fmaxf(rmax0, fmaxf(sacc[nt][0], sacc[nt][1]));
            rmax1 = fmaxf(rmax1, fmaxf(sacc[nt][2], sacc[nt][3]));
        }
        rmax0 = fmaxf(rmax0, __shfl_xor_sync(0xffffffffu, rmax0, 1));
        rmax0 = fmaxf(rmax0, __shfl_xor_sync(0xffffffffu, rmax0, 2));
        rmax1 = fmaxf(rmax1, __shfl_xor_sync(0xffffffffu, rmax1, 1));
        rmax1 = fmaxf(rmax1, __shfl_xor_sync(0xffffffffu, rmax1, 2));
        float newm0 = fmaxf(m0s, rmax0), newm1 = fmaxf(m1s, rmax1);
        float fac0 = __expf(m0s - newm0), fac1 = __expf(m1s - newm1);
        m0s = newm0; m1s = newm1;

        float rs0 = 0.0f, rs1 = 0.0f;
#pragma unroll
        for (int nt = 0; nt < 8; nt++) {
            float p0 = __expf(sacc[nt][0] - newm0);
            float p1 = __expf(sacc[nt][1] - newm0);
            float p2 = __expf(sacc[nt][2] - newm1);
            float p3 = __expf(sacc[nt][3] - newm1);
            rs0 += p0 + p1; rs1 += p2 + p3;
            int cn = nt * 8 + 2 * t;
            *(unsigned*)(Ps + prow0 + cn) = pk2(p0, p1);
            *(unsigned*)(Ps + prow1 + cn) = pk2(p2, p3);
        }
        rs0 += __shfl_xor_sync(0xffffffffu, rs0, 1);
        rs0 += __shfl_xor_sync(0xffffffffu, rs0, 2);
        rs1 += __shfl_xor_sync(0xffffffffu, rs1, 1);
        rs1 += __shfl_xor_sync(0xffffffffu, rs1, 2);
        l0s = l0s * fac0 + rs0;
        l1s = l1s * fac1 + rs1;
#pragma unroll
        for (int nt = 0; nt < 16; nt++) {
            oacc[nt][0] *= fac0; oacc[nt][1] *= fac0;
            oacc[nt][2] *= fac1; oacc[nt][3] *= fac1;
        }
        __syncwarp();

#pragma unroll
        for (int kk = 0; kk < 4; kk++) {
            int k0 = kk * 16 + 2 * t;
            unsigned pa[4];
            pa[0] = *(const unsigned*)(Ps + prow0 + k0);
            pa[1] = *(const unsigned*)(Ps + prow1 + k0);
            pa[2] = *(const unsigned*)(Ps + prow0 + k0 + 8);
            pa[3] = *(const unsigned*)(Ps + prow1 + k0 + 8);
#pragma unroll
            for (int nt = 0; nt < 16; nt++) {
                int d = nt * 8 + g;
                unsigned b0 = *(const unsigned*)(Vt + d * 72 + k0);
                unsigned b1 = *(const unsigned*)(Vt + d * 72 + k0 + 8);
                mma_f16(oacc[nt], pa, b0, b1);
            }
        }
        __syncthreads();
    }

    float inv0 = 1.0f / l0s, inv1 = 1.0f / l1s;
    int r0 = qbase + warp * 16 + g, r1 = r0 + 8;
#pragma unroll
    for (int nt = 0; nt < 16; nt++) {
        int d = hh * HD + nt * 8 + 2 * t;
        if (r0 < S)
            *(unsigned*)(obuf + (size_t)r0 * DIMC + d) =
                pk2(oacc[nt][0] * inv0, oacc[nt][1] * inv0);
        if (r1 < S)
            *(unsigned*)(obuf + (size_t)r1 * DIMC + d) =
                pk2(oacc[nt][2] * inv1, oacc[nt][3] * inv1);
    }
}

// ---------------------------------------------------------------------------
extern "C" void kernel_launch(void* const* d_in, const int* in_sizes, int n_in,
                              void* d_out, int out_size)
{
    const float* x   = (const float*)d_in[0];
    const float* th  = (const float*)d_in[1];
    const float* ck  = (const float*)d_in[2];
    const float* cv  = (const float*)d_in[3];
    const float* wq  = (const float*)d_in[4];
    const float* bq  = (const float*)d_in[5];
    const float* wk  = (const float*)d_in[6];
    const float* bk  = (const float*)d_in[7];
    const float* wv  = (const float*)d_in[8];
    const float* bv  = (const float*)d_in[9];
    const float* wo  = (const float*)d_in[10];
    const float* bo  = (const float*)d_in[11];
    const float* gq  = (const float*)d_in[12];
    const float* gk  = (const float*)d_in[13];
    const int* p_gh  = (const int*)d_in[15];
    const int* p_gw  = (const int*)d_in[16];
    const int* p_cs  = (const int*)d_in[17];
    const int* p_ge  = (const int*)d_in[18];
    const int* p_le  = (const int*)d_in[19];
    float* out = (float*)d_out;

    int S = in_sizes[0] / DIMC;

    float *qp, *kp, *vp;
    __half *xhp, *ohp, *whp;
    cudaGetSymbolAddress((void**)&qp, g_q);
    cudaGetSymbolAddress((void**)&kp, g_k);
    cudaGetSymbolAddress((void**)&vp, g_v);
    cudaGetSymbolAddress((void**)&xhp, g_xh);
    cudaGetSymbolAddress((void**)&ohp, g_oh);
    cudaGetSymbolAddress((void**)&whp, g_wh);

    int wn8 = DIMC * DIMC / 8;
    prep_half_kernel<<<(4 * wn8 + 255) / 256, 256>>>(wq, wk, wv, wo, whp, wn8);
    int xn8 = S * DIMC / 8;
    prep_half_kernel<<<(xn8 + 255) / 256, 256>>>(x, 0, 0, 0, xhp, xn8);

    size_t gsm = 30720;  // 2 stages * 7680 halves
    cudaFuncSetAttribute(gemm_f16_kernel, cudaFuncAttributeMaxDynamicSharedMemorySize,
                         (int)gsm);
    dim3 gqkv((S + 63) / 64, DIMC / 128, 3);
    gemm_f16_kernel<<<gqkv, 128, gsm>>>(xhp, whp, bq, bk, bv, qp, kp, vp, S);

    norm_rope_kernel<<<dim3(S, 2), 256>>>(qp, kp, gq, gk, th, p_gh, p_gw, p_cs);

    prep_kv_kernel<<<dim3(PADW / 64, NHEADS), 256>>>(kp, vp, ck, cv, S,
                                                     p_cs, p_ge, p_le);

    size_t fsm = (size_t)(35840 + 64 * 72) * sizeof(__half);  // 80896 B
    cudaFuncSetAttribute(flash_f16_kernel, cudaFuncAttributeMaxDynamicSharedMemorySize,
                         (int)fsm);
    flash_f16_kernel<<<dim3((S + 63) / 64, NHEADS), 128, fsm>>>(
        qp, ohp, S, p_cs, p_ge, p_le);

    dim3 go((S + 63) / 64, DIMC / 128, 1);
    gemm_f16_kernel<<<go, 128, gsm>>>(ohp, whp + (size_t)3 * DIMC * DIMC,
                                      bo, bo, bo, out, out, out, S);
}

// round 10
// speedup vs baseline: 7.5354x; 1.0640x over previous
#include <cuda_runtime.h>
#include <cuda_fp16.h>
#include <math.h>

#define DIMC 1536
#define NHEADS 12
#define HD 128
#define MAX_ATTN_W 5632
#define MAXS 3200
#define PADW 5632

__device__ float  g_q[MAXS * DIMC];
__device__ float  g_k[MAXS * DIMC];
__device__ float  g_v[MAXS * DIMC];
__device__ __half g_xh[MAXS * DIMC];
__device__ __half g_oh[MAXS * DIMC];
__device__ __half g_wh[4 * DIMC * DIMC];
__device__ __half g_kw[NHEADS * PADW * HD];     // [h][key][d]
__device__ __half g_vwT[NHEADS * HD * PADW];    // [h][d][key]

__device__ __forceinline__ unsigned pk2(float a, float b) {
    __half2 h = __floats2half2_rn(a, b);
    return *(unsigned*)&h;
}

__device__ __forceinline__ void mma_f16(float* d, const unsigned* a,
                                        unsigned b0, unsigned b1) {
    asm volatile(
        "mma.sync.aligned.m16n8k16.row.col.f32.f16.f16.f32 "
        "{%0,%1,%2,%3}, {%4,%5,%6,%7}, {%8,%9}, {%0,%1,%2,%3};\n"
        : "+f"(d[0]), "+f"(d[1]), "+f"(d[2]), "+f"(d[3])
        : "r"(a[0]), "r"(a[1]), "r"(a[2]), "r"(a[3]), "r"(b0), "r"(b1));
}

__device__ __forceinline__ void ldsm4(unsigned& r0, unsigned& r1,
                                      unsigned& r2, unsigned& r3, unsigned a) {
    asm volatile("ldmatrix.sync.aligned.m8n8.x4.shared.b16 {%0,%1,%2,%3}, [%4];"
                 : "=r"(r0), "=r"(r1), "=r"(r2), "=r"(r3) : "r"(a));
}

__device__ __forceinline__ unsigned s2u(const void* p) {
    return (unsigned)__cvta_generic_to_shared(p);
}

__device__ __forceinline__ void cpa16(void* dst_smem, const void* src) {
    unsigned d = (unsigned)__cvta_generic_to_shared(dst_smem);
    asm volatile("cp.async.cg.shared.global [%0], [%1], 16;\n" :: "r"(d), "l"(src));
}
#define CP_COMMIT() asm volatile("cp.async.commit_group;\n" ::: "memory")

// ---------------------------------------------------------------------------
__global__ __launch_bounds__(256) void prep_half_kernel(
    const float* __restrict__ s0, const float* __restrict__ s1,
    const float* __restrict__ s2, const float* __restrict__ s3,
    __half* __restrict__ dst, int n8_each)
{
    int i = blockIdx.x * 256 + threadIdx.x;
    int total = (s1 ? 4 : 1) * n8_each;
    if (i >= total) return;
    int wsel = i / n8_each, r = i - wsel * n8_each;
    const float* src = (wsel == 0) ? s0 : (wsel == 1) ? s1 : (wsel == 2) ? s2 : s3;
    float4 v0 = ((const float4*)src)[2 * r];
    float4 v1 = ((const float4*)src)[2 * r + 1];
    uint4 o;
    o.x = pk2(v0.x, v0.y); o.y = pk2(v0.z, v0.w);
    o.z = pk2(v1.x, v1.y); o.w = pk2(v1.z, v1.w);
    ((uint4*)dst)[i] = o;
}

// ---------------------------------------------------------------------------
__global__ __launch_bounds__(256) void prep_kv_kernel(
    const float* __restrict__ kbuf, const float* __restrict__ vbuf,
    const float* __restrict__ cache_k, const float* __restrict__ cache_v, int S,
    const int* __restrict__ p_cs, const int* __restrict__ p_ge,
    const int* __restrict__ p_le)
{
    __shared__ __half vts[128][72];

    int cs = *p_cs, ge = *p_ge, le = *p_le;
    int local_end = le + cs + S - ge;
    int local_start = local_end - S;
    int win_start = local_end - MAX_ATTN_W;
    if (win_start < 0) win_start = 0;
    int L = local_end - win_start;

    int h = blockIdx.y;
    int j0 = blockIdx.x * 64;
    int tid = threadIdx.x;

#pragma unroll
    for (int i = 0; i < 8; i++) {
        int idx = tid + i * 256;
        int key = idx >> 5, c4 = idx & 31;
        int j = j0 + key;
        float4 kv = make_float4(0.f, 0.f, 0.f, 0.f), vv = kv;
        if (j < L) {
            int jg = win_start + j;
            const float *ks, *vs;
            if (jg < local_start) {
                size_t o = ((size_t)jg * NHEADS + h) * HD + c4 * 4;
                ks = cache_k + o; vs = cache_v + o;
            } else {
                size_t o = (size_t)(jg - local_start) * DIMC + h * HD + c4 * 4;
                ks = kbuf + o; vs = vbuf + o;
            }
            kv = *(const float4*)ks; vv = *(const float4*)vs;
        }
        uint2 ko; ko.x = pk2(kv.x, kv.y); ko.y = pk2(kv.z, kv.w);
        *(uint2*)(g_kw + ((size_t)h * PADW + j) * HD + c4 * 4) = ko;
        vts[c4 * 4 + 0][key] = __float2half_rn(vv.x);
        vts[c4 * 4 + 1][key] = __float2half_rn(vv.y);
        vts[c4 * 4 + 2][key] = __float2half_rn(vv.z);
        vts[c4 * 4 + 3][key] = __float2half_rn(vv.w);
    }
    __syncthreads();
#pragma unroll
    for (int i = 0; i < 4; i++) {
        int idx = tid + i * 256;
        int d = idx >> 3, c = idx & 7;
        *(uint4*)(g_vwT + ((size_t)h * HD + d) * PADW + j0 + c * 8) =
            *(uint4*)&vts[d][c * 8];
    }
}

// ---------------------------------------------------------------------------
// GEMM fp16 with ldmatrix fragment loads. BM=64, BN=128, BK=32, 128 thr.
// ---------------------------------------------------------------------------
__global__ __launch_bounds__(128) void gemm_f16_kernel(
    const __half* __restrict__ A, const __half* __restrict__ Wbase,
    const float* __restrict__ b0p, const float* __restrict__ b1p,
    const float* __restrict__ b2p, float* __restrict__ C0,
    float* __restrict__ C1, float* __restrict__ C2, int M)
{
    extern __shared__ float smf[];
    __half* sh = (__half*)smf;
    int z = blockIdx.z;
    const __half* W = Wbase + (size_t)z * DIMC * DIMC;
    const float* bias = (z == 0) ? b0p : (z == 1) ? b1p : b2p;
    float* C = (z == 0) ? C0 : (z == 1) ? C1 : C2;

    int tid = threadIdx.x, warp = tid >> 5, lane = tid & 31;
    int g = lane >> 2, t = lane & 3;
    int wm = warp * 16;
    int bm = blockIdx.x * 64, bn = blockIdx.y * 128;

    // ldmatrix per-lane offsets (halves)
    int lr = lane & 7;
    int prB = (((lane >> 3) & 2) << 2) + lr;   // B-style rows
    int pcB = ((lane >> 3) & 1) * 8;
    int prA = (((lane >> 3) & 1) << 3) + lr;   // A-style rows
    int pcA = ((lane >> 4) & 1) * 8;

    float acc[16][4];
#pragma unroll
    for (int nt = 0; nt < 16; nt++)
#pragma unroll
        for (int i = 0; i < 4; i++) acc[nt][i] = 0.0f;

#define GF(stg, kt)                                                           \
    {                                                                         \
        __half* As_ = sh + (stg) * 7680;                                      \
        __half* Bs_ = As_ + 2560;                                             \
        const __half* Ag_ = A + (size_t)bm * DIMC + (kt) * 32;                \
        const __half* Wg_ = W + (size_t)bn * DIMC + (kt) * 32;                \
        _Pragma("unroll")                                                     \
        for (int j = 0; j < 2; j++) {                                         \
            int idx = tid + j * 128;                                          \
            int row = idx >> 2, c = idx & 3;                                  \
            cpa16(As_ + row * 40 + c * 8, Ag_ + (size_t)row * DIMC + c * 8);  \
        }                                                                     \
        _Pragma("unroll")                                                     \
        for (int j = 0; j < 4; j++) {                                         \
            int idx = tid + j * 128;                                          \
            int row = idx >> 2, c = idx & 3;                                  \
            cpa16(Bs_ + row * 40 + c * 8, Wg_ + (size_t)row * DIMC + c * 8);  \
        }                                                                     \
    }

    GF(0, 0); CP_COMMIT();
    for (int kt = 0; kt < 48; kt++) {
        int s = kt & 1;
        if (kt + 1 < 48) {
            GF(s ^ 1, kt + 1); CP_COMMIT();
            asm volatile("cp.async.wait_group 1;\n" ::: "memory");
        } else {
            asm volatile("cp.async.wait_group 0;\n" ::: "memory");
        }
        __syncthreads();
        const __half* As = sh + s * 7680;
        const __half* Bs = As + 2560;
        unsigned abase = s2u(As) + ((wm + prA) * 40 + pcA) * 2;
        unsigned bbase = s2u(Bs) + (prB * 40 + pcB) * 2;
#pragma unroll
        for (int kst = 0; kst < 2; kst++) {
            unsigned af[4];
            ldsm4(af[0], af[1], af[2], af[3], abase + kst * 32);
#pragma unroll
            for (int np = 0; np < 8; np++) {
                unsigned b0, b1, b2, b3;
                ldsm4(b0, b1, b2, b3, bbase + (np * 16 * 40) * 2 + kst * 32);
                mma_f16(acc[np * 2], af, b0, b1);
                mma_f16(acc[np * 2 + 1], af, b2, b3);
            }
        }
        __syncthreads();
    }
    int m0 = bm + wm + g, m1 = m0 + 8;
#pragma unroll
    for (int nt = 0; nt < 16; nt++) {
        int n = bn + nt * 8 + 2 * t;
        float bb0 = bias[n], bb1 = bias[n + 1];
        if (m0 < M)
            *(float2*)(C + (size_t)m0 * DIMC + n) =
                make_float2(acc[nt][0] + bb0, acc[nt][1] + bb1);
        if (m1 < M)
            *(float2*)(C + (size_t)m1 * DIMC + n) =
                make_float2(acc[nt][2] + bb0, acc[nt][3] + bb1);
    }
}

// ---------------------------------------------------------------------------
__global__ __launch_bounds__(256) void norm_rope_kernel(
    float* __restrict__ qb, float* __restrict__ kb,
    const float* __restrict__ gq, const float* __restrict__ gk,
    const float* __restrict__ theta,
    const int* __restrict__ p_gh, const int* __restrict__ p_gw,
    const int* __restrict__ p_cs)
{
    __shared__ float row[DIMC];
    __shared__ float red[256];

    int srow = blockIdx.x;
    int which = blockIdx.y;
    float* buf = which ? kb : qb;
    const float* g = which ? gk : gq;
    float* rptr = buf + (size_t)srow * DIMC;

    int tid = threadIdx.x;
    float vals[6];
    float ss = 0.0f;
#pragma unroll
    for (int q = 0; q < 6; q++) {
        int d = tid + q * 256;
        float v = rptr[d];
        vals[q] = v;
        ss += v * v;
    }
    red[tid] = ss;
    __syncthreads();
    for (int o = 128; o > 0; o >>= 1) {
        if (tid < o) red[tid] += red[tid + o];
        __syncthreads();
    }
    float scale = rsqrtf(red[0] * (1.0f / DIMC) + 1e-6f);
#pragma unroll
    for (int q = 0; q < 6; q++) {
        int d = tid + q * 256;
        row[d] = vals[q] * scale * g[d];
    }
    __syncthreads();

    int gh = *p_gh, gw = *p_gw, cs = *p_cs;
    int fs = gh * gw;
    int sf = cs / fs;
    int f = srow / fs;
    int rem = srow - f * fs;
    int h = rem / gw;
    int w = rem - h * gw;

    for (int p = tid; p < NHEADS * (HD / 2); p += 256) {
        int head = p >> 6;
        int i = p & 63;
        int trow = (i < 22) ? (sf + f) : ((i < 43) ? h : w);
        float ang = theta[trow * (HD / 2) + i];
        float sn, cn;
        __sincosf(ang, &sn, &cn);
        int d0 = head * HD + 2 * i;
        float xr = row[d0], xi = row[d0 + 1];
        rptr[d0]     = xr * cn - xi * sn;
        rptr[d0 + 1] = xr * sn + xi * cn;
    }
}

// ---------------------------------------------------------------------------
// Flash attention fp16 + ldmatrix. BM=64 (4 warps x 16 rows), BN=64 keys.
// ---------------------------------------------------------------------------
__global__ __launch_bounds__(128) void flash_f16_kernel(
    const float* __restrict__ qbuf, __half* __restrict__ obuf, int S,
    const int* __restrict__ p_cs, const int* __restrict__ p_ge,
    const int* __restrict__ p_le)
{
    extern __shared__ float smf[];
    __half* sh = (__half*)smf;
    __half* Ps = sh + 35840;     // 64*72 halves

    int cs = *p_cs, ge = *p_ge, le = *p_le;
    int local_end = le + cs + S - ge;
    int win_start = local_end - MAX_ATTN_W;
    if (win_start < 0) win_start = 0;
    int L = local_end - win_start;

    int hh = blockIdx.y;
    int qbase = blockIdx.x * 64;
    int tid = threadIdx.x, warp = tid >> 5, lane = tid & 31;
    int g = lane >> 2, t = lane & 3;
    const float scale = 0.08838834764831845f;

    int lr = lane & 7;
    int prB = (((lane >> 3) & 2) << 2) + lr;
    int pcB = ((lane >> 3) & 1) * 8;
    int prA = (((lane >> 3) & 1) << 3) + lr;
    int pcA = ((lane >> 4) & 1) * 8;

    unsigned qa[8][4];
    {
        int r0 = qbase + warp * 16 + g, r1 = r0 + 8;
        const float* q0p = qbuf + (size_t)r0 * DIMC + hh * HD;
        const float* q1p = qbuf + (size_t)r1 * DIMC + hh * HD;
        bool v0 = r0 < S, v1 = r1 < S;
#pragma unroll
        for (int ks = 0; ks < 8; ks++) {
            int c = ks * 16 + 2 * t;
            qa[ks][0] = v0 ? pk2(q0p[c] * scale, q0p[c + 1] * scale) : 0u;
            qa[ks][1] = v1 ? pk2(q1p[c] * scale, q1p[c + 1] * scale) : 0u;
            qa[ks][2] = v0 ? pk2(q0p[c + 8] * scale, q0p[c + 9] * scale) : 0u;
            qa[ks][3] = v1 ? pk2(q1p[c + 8] * scale, q1p[c + 9] * scale) : 0u;
        }
    }

    float oacc[16][4];
#pragma unroll
    for (int nt = 0; nt < 16; nt++)
#pragma unroll
        for (int i = 0; i < 4; i++) oacc[nt][i] = 0.0f;
    float m0s = -1e30f, m1s = -1e30f, l0s = 0.0f, l1s = 0.0f;

    int prow0 = (warp * 16 + g) * 72, prow1 = prow0 + 8 * 72;
    unsigned pabase = s2u(Ps) + ((warp * 16 + prA) * 72 + pcA) * 2;
    int nkt = (L + 63) >> 6;

    const __half* kwb = g_kw + (size_t)hh * PADW * HD;
    const __half* vwb = g_vwT + (size_t)hh * HD * PADW;

#define KVF(stg, kt)                                                          \
    {                                                                         \
        __half* Ks_ = sh + (stg) * 17920;                                     \
        __half* Vt_ = Ks_ + 8704;                                             \
        const __half* kb_ = kwb + (size_t)(kt) * 64 * HD;                     \
        _Pragma("unroll")                                                     \
        for (int j = 0; j < 8; j++) {                                         \
            int idx = tid + j * 128;                                          \
            int row = idx >> 4, c = idx & 15;                                 \
            cpa16(Ks_ + row * 136 + c * 8, kb_ + (size_t)row * HD + c * 8);   \
        }                                                                     \
        _Pragma("unroll")                                                     \
        for (int j = 0; j < 8; j++) {                                         \
            int idx = tid + j * 128;                                          \
            int row = idx >> 3, c = idx & 7;                                  \
            cpa16(Vt_ + row * 72 + c * 8,                                     \
                  vwb + (size_t)row * PADW + (kt) * 64 + c * 8);              \
        }                                                                     \
    }

    KVF(0, 0); CP_COMMIT();
    for (int kt = 0; kt < nkt; kt++) {
        int s = kt & 1;
        if (kt + 1 < nkt) {
            KVF(s ^ 1, kt + 1); CP_COMMIT();
            asm volatile("cp.async.wait_group 1;\n" ::: "memory");
        } else {
            asm volatile("cp.async.wait_group 0;\n" ::: "memory");
        }
        __syncthreads();
        const __half* Ks = sh + s * 17920;
        const __half* Vt = Ks + 8704;
        unsigned kbase = s2u(Ks) + (prB * 136 + pcB) * 2;
        unsigned vbase = s2u(Vt) + (prB * 72 + pcB) * 2;

        // S = Q K^T  (B frags via ldmatrix x4: 2 key-groups per load)
        float sacc[8][4];
#pragma unroll
        for (int nt = 0; nt < 8; nt++)
#pragma unroll
            for (int i = 0; i < 4; i++) sacc[nt][i] = 0.0f;
#pragma unroll
        for (int ks = 0; ks < 8; ks++) {
#pragma unroll
            for (int np = 0; np < 4; np++) {
                unsigned b0, b1, b2, b3;
                ldsm4(b0, b1, b2, b3, kbase + (np * 16 * 136) * 2 + ks * 32);
                mma_f16(sacc[np * 2], qa[ks], b0, b1);
                mma_f16(sacc[np * 2 + 1], qa[ks], b2, b3);
            }
        }

        int colb = kt * 64 + 2 * t;
        float rmax0 = -1e30f, rmax1 = -1e30f;
#pragma unroll
        for (int nt = 0; nt < 8; nt++) {
            int c = colb + nt * 8;
            if (c >= L)     { sacc[nt][0] = -1e30f; sacc[nt][2] = -1e30f; }
            if (c + 1 >= L) { sacc[nt][1] = -1e30f; sacc[nt][3] = -1e30f; }
            rmax0 = fmaxf(rmax0, fmaxf(sacc[nt][0], sacc[nt][1]));
            rmax1 = fmaxf(rmax1, fmaxf(sacc[nt][2], sacc[nt][3]));
        }
        rmax0 = fmaxf(rmax0, __shfl_xor_sync(0xffffffffu, rmax0, 1));
        rmax0 = fmaxf(rmax0, __shfl_xor_sync(0xffffffffu, rmax0, 2));
        rmax1 = fmaxf(rmax1, __shfl_xor_sync(0xffffffffu, rmax1, 1));
        rmax1 = fmaxf(rmax1, __shfl_xor_sync(0xffffffffu, rmax1, 2));
        float newm0 = fmaxf(m0s, rmax0), newm1 = fmaxf(m1s, rmax1);
        float fac0 = __expf(m0s - newm0), fac1 = __expf(m1s - newm1);
        m0s = newm0; m1s = newm1;

        float rs0 = 0.0f, rs1 = 0.0f;
#pragma unroll
        for (int nt = 0; nt < 8; nt++) {
            float p0 = __expf(sacc[nt][0] - newm0);
            float p1 = __expf(sacc[nt][1] - newm0);
            float p2 = __expf(sacc[nt][2] - newm1);
            float p3 = __expf(sacc[nt][3] - newm1);
            rs0 += p0 + p1; rs1 += p2 + p3;
            int cn = nt * 8 + 2 * t;
            *(unsigned*)(Ps + prow0 + cn) = pk2(p0, p1);
            *(unsigned*)(Ps + prow1 + cn) = pk2(p2, p3);
        }
        rs0 += __shfl_xor_sync(0xffffffffu, rs0, 1);
        rs0 += __shfl_xor_sync(0xffffffffu, rs0, 2);
        rs1 += __shfl_xor_sync(0xffffffffu, rs1, 1);
        rs1 += __shfl_xor_sync(0xffffffffu, rs1, 2);
        l0s = l0s * fac0 + rs0;
        l1s = l1s * fac1 + rs1;
#pragma unroll
        for (int nt = 0; nt < 16; nt++) {
            oacc[nt][0] *= fac0; oacc[nt][1] *= fac0;
            oacc[nt][2] *= fac1; oacc[nt][3] *= fac1;
        }
        __syncwarp();

        // O += P V  (P a-frags + V^T b-frags via ldmatrix)
#pragma unroll
        for (int kk = 0; kk < 4; kk++) {
            unsigned pa[4];
            ldsm4(pa[0], pa[1], pa[2], pa[3], pabase + kk * 32);
#pragma unroll
            for (int np = 0; np < 8; np++) {
                unsigned b0, b1, b2, b3;
                ldsm4(b0, b1, b2, b3, vbase + (np * 16 * 72) * 2 + kk * 32);
                mma_f16(oacc[np * 2], pa, b0, b1);
                mma_f16(oacc[np * 2 + 1], pa, b2, b3);
            }
        }
        __syncthreads();
    }

    float inv0 = 1.0f / l0s, inv1 = 1.0f / l1s;
    int r0 = qbase + warp * 16 + g, r1 = r0 + 8;
#pragma unroll
    for (int nt = 0; nt < 16; nt++) {
        int d = hh * HD + nt * 8 + 2 * t;
        if (r0 < S)
            *(unsigned*)(obuf + (size_t)r0 * DIMC + d) =
                pk2(oacc[nt][0] * inv0, oacc[nt][1] * inv0);
        if (r1 < S)
            *(unsigned*)(obuf + (size_t)r1 * DIMC + d) =
                pk2(oacc[nt][2] * inv1, oacc[nt][3] * inv1);
    }
}

// ---------------------------------------------------------------------------
extern "C" void kernel_launch(void* const* d_in, const int* in_sizes, int n_in,
                              void* d_out, int out_size)
{
    const float* x   = (const float*)d_in[0];
    const float* th  = (const float*)d_in[1];
    const float* ck  = (const float*)d_in[2];
    const float* cv  = (const float*)d_in[3];
    const float* wq  = (const float*)d_in[4];
    const float* bq  = (const float*)d_in[5];
    const float* wk  = (const float*)d_in[6];
    const float* bk  = (const float*)d_in[7];
    const float* wv  = (const float*)d_in[8];
    const float* bv  = (const float*)d_in[9];
    const float* wo  = (const float*)d_in[10];
    const float* bo  = (const float*)d_in[11];
    const float* gq  = (const float*)d_in[12];
    const float* gk  = (const float*)d_in[13];
    const int* p_gh  = (const int*)d_in[15];
    const int* p_gw  = (const int*)d_in[16];
    const int* p_cs  = (const int*)d_in[17];
    const int* p_ge  = (const int*)d_in[18];
    const int* p_le  = (const int*)d_in[19];
    float* out = (float*)d_out;

    int S = in_sizes[0] / DIMC;

    float *qp, *kp, *vp;
    __half *xhp, *ohp, *whp;
    cudaGetSymbolAddress((void**)&qp, g_q);
    cudaGetSymbolAddress((void**)&kp, g_k);
    cudaGetSymbolAddress((void**)&vp, g_v);
    cudaGetSymbolAddress((void**)&xhp, g_xh);
    cudaGetSymbolAddress((void**)&ohp, g_oh);
    cudaGetSymbolAddress((void**)&whp, g_wh);

    int wn8 = DIMC * DIMC / 8;
    prep_half_kernel<<<(4 * wn8 + 255) / 256, 256>>>(wq, wk, wv, wo, whp, wn8);
    int xn8 = S * DIMC / 8;
    prep_half_kernel<<<(xn8 + 255) / 256, 256>>>(x, 0, 0, 0, xhp, xn8);

    size_t gsm = 30720;
    cudaFuncSetAttribute(gemm_f16_kernel, cudaFuncAttributeMaxDynamicSharedMemorySize,
                         (int)gsm);
    dim3 gqkv((S + 63) / 64, DIMC / 128, 3);
    gemm_f16_kernel<<<gqkv, 128, gsm>>>(xhp, whp, bq, bk, bv, qp, kp, vp, S);

    norm_rope_kernel<<<dim3(S, 2), 256>>>(qp, kp, gq, gk, th, p_gh, p_gw, p_cs);

    prep_kv_kernel<<<dim3(PADW / 64, NHEADS), 256>>>(kp, vp, ck, cv, S,
                                                     p_cs, p_ge, p_le);

    size_t fsm = (size_t)(35840 + 64 * 72) * sizeof(__half);
    cudaFuncSetAttribute(flash_f16_kernel, cudaFuncAttributeMaxDynamicSharedMemorySize,
                         (int)fsm);
    flash_f16_kernel<<<dim3((S + 63) / 64, NHEADS), 128, fsm>>>(
        qp, ohp, S, p_cs, p_ge, p_le);

    dim3 go((S + 63) / 64, DIMC / 128, 1);
    gemm_f16_kernel<<<go, 128, gsm>>>(ohp, whp + (size_t)3 * DIMC * DIMC,
                                      bo, bo, bo, out, out, out, S);
}